// round 10
// baseline (speedup 1.0000x reference)
#include <cuda_runtime.h>
#include <math.h>

// Problem constants
#define Bsz    8
#define Tlen   1024
#define EMB    1024
#define NHEADS 16
#define HD     64
#define CHUNK  64

#define MTOT (Bsz * Tlen)          // 8192 rows

// ---------------------------------------------------------------------------
// Scratch (device globals — allocation-free per harness rules)
// ---------------------------------------------------------------------------
__device__ float g_q[MTOT * EMB];
__device__ float g_k[MTOT * EMB];
__device__ float g_v[MTOT * EMB];
__device__ float g_attn[MTOT * EMB];

// ---------------------------------------------------------------------------
// GEMM core: C[128,128] tile of A[M,K] * B[N,K]^T + bias, double-buffered.
// ---------------------------------------------------------------------------
#define BM 128
#define BN 128
#define BK 16
#define LDA (BM + 4)
#define LDB (BN + 4)
#define GK  1024   // K is always EMB

__device__ __forceinline__
void gemm_tile_body(const float* __restrict__ A, const float* __restrict__ B,
                    const float* __restrict__ bias, float* __restrict__ C,
                    int mBase, int nBase, int N)
{
    __shared__ float As[2][BK][LDA];
    __shared__ float Bs[2][BK][LDB];

    const int tid = threadIdx.x;
    const int tx = tid & 15;
    const int ty = tid >> 4;

    const int lr = tid >> 1;           // 0..127
    const int lc = (tid & 1) * 8;      // 0 or 8

    const float* Ag = A + (size_t)(mBase + lr) * GK + lc;
    const float* Bg = B + (size_t)(nBase + lr) * GK + lc;

    float acc[8][8];
#pragma unroll
    for (int i = 0; i < 8; i++)
#pragma unroll
        for (int j = 0; j < 8; j++) acc[i][j] = 0.f;

    {
        float4 a0 = *(const float4*)(Ag);
        float4 a1 = *(const float4*)(Ag + 4);
        float4 b0 = *(const float4*)(Bg);
        float4 b1 = *(const float4*)(Bg + 4);
        As[0][lc + 0][lr] = a0.x; As[0][lc + 1][lr] = a0.y;
        As[0][lc + 2][lr] = a0.z; As[0][lc + 3][lr] = a0.w;
        As[0][lc + 4][lr] = a1.x; As[0][lc + 5][lr] = a1.y;
        As[0][lc + 6][lr] = a1.z; As[0][lc + 7][lr] = a1.w;
        Bs[0][lc + 0][lr] = b0.x; Bs[0][lc + 1][lr] = b0.y;
        Bs[0][lc + 2][lr] = b0.z; Bs[0][lc + 3][lr] = b0.w;
        Bs[0][lc + 4][lr] = b1.x; Bs[0][lc + 5][lr] = b1.y;
        Bs[0][lc + 6][lr] = b1.z; Bs[0][lc + 7][lr] = b1.w;
    }
    __syncthreads();

    int buf = 0;
    for (int k0 = 0; k0 < GK; k0 += BK) {
        float4 pa0, pa1, pb0, pb1;
        const bool more = (k0 + BK) < GK;
        if (more) {
            pa0 = *(const float4*)(Ag + k0 + BK);
            pa1 = *(const float4*)(Ag + k0 + BK + 4);
            pb0 = *(const float4*)(Bg + k0 + BK);
            pb1 = *(const float4*)(Bg + k0 + BK + 4);
        }

#pragma unroll
        for (int kk = 0; kk < BK; kk++) {
            float4 aL = *(const float4*)(&As[buf][kk][ty * 4]);
            float4 aH = *(const float4*)(&As[buf][kk][ty * 4 + 64]);
            float4 bL = *(const float4*)(&Bs[buf][kk][tx * 4]);
            float4 bH = *(const float4*)(&Bs[buf][kk][tx * 4 + 64]);
            float am[8] = {aL.x, aL.y, aL.z, aL.w, aH.x, aH.y, aH.z, aH.w};
            float bn[8] = {bL.x, bL.y, bL.z, bL.w, bH.x, bH.y, bH.z, bH.w};
#pragma unroll
            for (int i = 0; i < 8; i++)
#pragma unroll
                for (int j = 0; j < 8; j++)
                    acc[i][j] = fmaf(am[i], bn[j], acc[i][j]);
        }

        if (more) {
            int nb = buf ^ 1;
            As[nb][lc + 0][lr] = pa0.x; As[nb][lc + 1][lr] = pa0.y;
            As[nb][lc + 2][lr] = pa0.z; As[nb][lc + 3][lr] = pa0.w;
            As[nb][lc + 4][lr] = pa1.x; As[nb][lc + 5][lr] = pa1.y;
            As[nb][lc + 6][lr] = pa1.z; As[nb][lc + 7][lr] = pa1.w;
            Bs[nb][lc + 0][lr] = pb0.x; Bs[nb][lc + 1][lr] = pb0.y;
            Bs[nb][lc + 2][lr] = pb0.z; Bs[nb][lc + 3][lr] = pb0.w;
            Bs[nb][lc + 4][lr] = pb1.x; Bs[nb][lc + 5][lr] = pb1.y;
            Bs[nb][lc + 6][lr] = pb1.z; Bs[nb][lc + 7][lr] = pb1.w;
            __syncthreads();
            buf = nb;
        }
    }

    const int colL = nBase + tx * 4;
    const int colH = colL + 64;
    float4 bvL = *(const float4*)(bias + colL);
    float4 bvH = *(const float4*)(bias + colH);

#pragma unroll
    for (int hm = 0; hm < 2; hm++) {
#pragma unroll
        for (int i = 0; i < 4; i++) {
            int row = mBase + ty * 4 + i + hm * 64;
            int ii = hm * 4 + i;
            float4 oL, oH;
            oL.x = acc[ii][0] + bvL.x; oL.y = acc[ii][1] + bvL.y;
            oL.z = acc[ii][2] + bvL.z; oL.w = acc[ii][3] + bvL.w;
            oH.x = acc[ii][4] + bvH.x; oH.y = acc[ii][5] + bvH.y;
            oH.z = acc[ii][6] + bvH.z; oH.w = acc[ii][7] + bvH.w;
            *(float4*)(C + (size_t)row * N + colL) = oL;
            *(float4*)(C + (size_t)row * N + colH) = oH;
        }
    }
}

// Fused QKV projection: grid.x = 24 (3 matrices x 8 n-tiles), grid.y = 64.
__global__ __launch_bounds__(256)
void gemm_qkv(const float* __restrict__ x,
              const float* __restrict__ Wq, const float* __restrict__ Wk,
              const float* __restrict__ Wv,
              const float* __restrict__ bq, const float* __restrict__ bk,
              const float* __restrict__ bv,
              float* __restrict__ q, float* __restrict__ k, float* __restrict__ v)
{
    const int sel = blockIdx.x >> 3;
    const int nb  = blockIdx.x & 7;
    const float* B    = (sel == 0) ? Wq : (sel == 1) ? Wk : Wv;
    const float* bias = (sel == 0) ? bq : (sel == 1) ? bk : bv;
    float* C          = (sel == 0) ? q  : (sel == 1) ? k  : v;
    gemm_tile_body(x, B, bias, C, blockIdx.y * BM, nb * BN, EMB);
}

// Single GEMM (output projection)
__global__ __launch_bounds__(256)
void gemm_nt_bias(const float* __restrict__ A, const float* __restrict__ B,
                  const float* __restrict__ bias, float* __restrict__ C)
{
    gemm_tile_body(A, B, bias, C, blockIdx.y * BM, blockIdx.x * BN, EMB);
}

// ---------------------------------------------------------------------------
// Fused attention, flash-style. 128q x 64k tile, 256 threads = 32 ty x 8 tx.
// S phase:  thread = 4q x 8k over full d=64  (micro 4x8).
// PV phase: thread = 4q x 8d over full k=64  (no cross-lane combine needed).
// Ps rows are produced AND consumed within one warp -> __syncwarp only.
// smem = 103.4 KB -> 2 CTAs/SM (16 warps). __launch_bounds__(256,2).
// Mask: key masked iff same 64-chunk as query and key>query. With AKT=64 the
// diagonal tile for row qr is kt == qt*2 + (qr>>6); inside it mask
// (tx*8+j) > (qr & 63).
// ---------------------------------------------------------------------------
#define AQT 128
#define AKT 64
#define LDQ 132   // Qs [d=64][q=128+4]
#define LDK 68    // Ks [d=64][k=64+4]
#define LDVV 68   // Vs [k=64][d=64+4]
#define LDP 68    // Ps [q=128][k=64+4]

__global__ __launch_bounds__(256, 2)
void attn_kernel(const float* __restrict__ Q, const float* __restrict__ K,
                 const float* __restrict__ V, const float* __restrict__ scale_p,
                 float* __restrict__ O)
{
    extern __shared__ float smem[];
    float (*Qs)[LDQ]  = (float(*)[LDQ]) (smem);                              // [64][132]
    float (*Ks)[LDK]  = (float(*)[LDK]) (smem + HD * LDQ);                   // [64][68]
    float (*Vs)[LDVV] = (float(*)[LDVV])(smem + HD * LDQ + HD * LDK);        // [64][68]
    float (*Ps)[LDP]  = (float(*)[LDP]) (smem + HD * LDQ + HD * (LDK + LDVV)); // [128][68]

    const int tid = threadIdx.x;
    const int tx  = tid & 7;        // 8 key-groups (S) / 8 dim-groups (PV)
    const int ty  = tid >> 3;       // 32 q-groups of 4 rows
    const int qt = blockIdx.x, h = blockIdx.y, b = blockIdx.z;
    const float scale = scale_p[0];

    // ---- load Q tile transposed (d-major), scale folded in ----
    {
        const int r = tid >> 1;            // 0..127
        const int c = (tid & 1) * 32;      // 0 or 32
        const float* Qb = Q + ((size_t)b * Tlen + qt * AQT + r) * EMB + h * HD + c;
#pragma unroll
        for (int j = 0; j < 8; j++) {
            float4 q4 = *(const float4*)(Qb + 4 * j);
            Qs[c + 4 * j + 0][r] = q4.x * scale;
            Qs[c + 4 * j + 1][r] = q4.y * scale;
            Qs[c + 4 * j + 2][r] = q4.z * scale;
            Qs[c + 4 * j + 3][r] = q4.w * scale;
        }
    }

    float m[4], l[4], o[4][8];
#pragma unroll
    for (int i = 0; i < 4; i++) {
        m[i] = -INFINITY; l[i] = 0.f;
#pragma unroll
        for (int j = 0; j < 8; j++) o[i][j] = 0.f;
    }

    const int r2 = tid >> 2;          // 0..63
    const int c2 = (tid & 3) * 16;    // 0,16,32,48

    for (int kt = 0; kt < Tlen / AKT; kt++) {
        __syncthreads();   // K/V (+Qs first iter) safe to (over)write
        {
            const float* Kb = K + ((size_t)b * Tlen + kt * AKT + r2) * EMB + h * HD + c2;
            const float* Vb = V + ((size_t)b * Tlen + kt * AKT + r2) * EMB + h * HD + c2;
#pragma unroll
            for (int j = 0; j < 4; j++) {
                float4 k4 = *(const float4*)(Kb + 4 * j);
                Ks[c2 + 4 * j + 0][r2] = k4.x;
                Ks[c2 + 4 * j + 1][r2] = k4.y;
                Ks[c2 + 4 * j + 2][r2] = k4.z;
                Ks[c2 + 4 * j + 3][r2] = k4.w;
                *(float4*)&Vs[r2][c2 + 4 * j] = *(const float4*)(Vb + 4 * j);
            }
        }
        __syncthreads();

        // ---- S = (Q*scale) . K^T : 4x8 register tile over d=64 ----
        float s[4][8];
#pragma unroll
        for (int i = 0; i < 4; i++)
#pragma unroll
            for (int j = 0; j < 8; j++) s[i][j] = 0.f;

#pragma unroll 4
        for (int d = 0; d < HD; d++) {
            float4 qv = *(const float4*)&Qs[d][ty * 4];
            float4 kL = *(const float4*)&Ks[d][tx * 8];
            float4 kH = *(const float4*)&Ks[d][tx * 8 + 4];
            float qa[4] = {qv.x, qv.y, qv.z, qv.w};
            float kb8[8] = {kL.x, kL.y, kL.z, kL.w, kH.x, kH.y, kH.z, kH.w};
#pragma unroll
            for (int i = 0; i < 4; i++)
#pragma unroll
                for (int j = 0; j < 8; j++)
                    s[i][j] = fmaf(qa[i], kb8[j], s[i][j]);
        }

        // ---- mask (diagonal chunk only) ----
#pragma unroll
        for (int i = 0; i < 4; i++) {
            const int qr = ty * 4 + i;
            if (kt == qt * 2 + (qr >> 6)) {
                const int rel = qr & 63;
#pragma unroll
                for (int j = 0; j < 8; j++)
                    if (tx * 8 + j > rel) s[i][j] = -INFINITY;
            }
        }

        // ---- online softmax: reduce across the 8 tx lanes (bits 0..2) ----
#pragma unroll
        for (int i = 0; i < 4; i++) {
            float tm = fmaxf(fmaxf(fmaxf(s[i][0], s[i][1]), fmaxf(s[i][2], s[i][3])),
                             fmaxf(fmaxf(s[i][4], s[i][5]), fmaxf(s[i][6], s[i][7])));
            tm = fmaxf(tm, __shfl_xor_sync(0xffffffffu, tm, 1));
            tm = fmaxf(tm, __shfl_xor_sync(0xffffffffu, tm, 2));
            tm = fmaxf(tm, __shfl_xor_sync(0xffffffffu, tm, 4));
            float mnew = fmaxf(m[i], tm);
            float corr = __expf(m[i] - mnew);   // 0 when m == -inf

            float p[8];
            float ts = 0.f;
#pragma unroll
            for (int j = 0; j < 8; j++) {
                p[j] = __expf(s[i][j] - mnew);
                ts += p[j];
            }
            ts += __shfl_xor_sync(0xffffffffu, ts, 1);
            ts += __shfl_xor_sync(0xffffffffu, ts, 2);
            ts += __shfl_xor_sync(0xffffffffu, ts, 4);
            l[i] = l[i] * corr + ts;
            m[i] = mnew;
#pragma unroll
            for (int j = 0; j < 8; j++) o[i][j] *= corr;
            *(float4*)&Ps[ty * 4 + i][tx * 8]     = make_float4(p[0], p[1], p[2], p[3]);
            *(float4*)&Ps[ty * 4 + i][tx * 8 + 4] = make_float4(p[4], p[5], p[6], p[7]);
        }
        __syncwarp();   // Ps rows are warp-private: producer lanes == consumer lanes' warp

        // ---- O += P . V : rows ty*4.., dims tx*8.., all 64 keys ----
#pragma unroll 2
        for (int kk = 0; kk < AKT; kk += 4) {
            float4 v0L = *(const float4*)&Vs[kk + 0][tx * 8];
            float4 v0H = *(const float4*)&Vs[kk + 0][tx * 8 + 4];
            float4 v1L = *(const float4*)&Vs[kk + 1][tx * 8];
            float4 v1H = *(const float4*)&Vs[kk + 1][tx * 8 + 4];
            float4 v2L = *(const float4*)&Vs[kk + 2][tx * 8];
            float4 v2H = *(const float4*)&Vs[kk + 2][tx * 8 + 4];
            float4 v3L = *(const float4*)&Vs[kk + 3][tx * 8];
            float4 v3H = *(const float4*)&Vs[kk + 3][tx * 8 + 4];
            float vb[4][8] = {
                {v0L.x, v0L.y, v0L.z, v0L.w, v0H.x, v0H.y, v0H.z, v0H.w},
                {v1L.x, v1L.y, v1L.z, v1L.w, v1H.x, v1H.y, v1H.z, v1H.w},
                {v2L.x, v2L.y, v2L.z, v2L.w, v2H.x, v2H.y, v2H.z, v2H.w},
                {v3L.x, v3L.y, v3L.z, v3L.w, v3H.x, v3H.y, v3H.z, v3H.w},
            };
#pragma unroll
            for (int i = 0; i < 4; i++) {
                float4 pr = *(const float4*)&Ps[ty * 4 + i][kk];
                float pa[4] = {pr.x, pr.y, pr.z, pr.w};
#pragma unroll
                for (int t = 0; t < 4; t++)
#pragma unroll
                    for (int j = 0; j < 8; j++)
                        o[i][j] = fmaf(pa[t], vb[t][j], o[i][j]);
            }
        }
    }

    // ---- finalize + store (each thread owns its 4 rows x 8 dims) ----
#pragma unroll
    for (int i = 0; i < 4; i++) {
        float inv = 1.f / l[i];
        float* Ob = O + ((size_t)b * Tlen + qt * AQT + ty * 4 + i) * EMB
                      + h * HD + tx * 8;
        *(float4*)Ob       = make_float4(o[i][0] * inv, o[i][1] * inv,
                                         o[i][2] * inv, o[i][3] * inv);
        *(float4*)(Ob + 4) = make_float4(o[i][4] * inv, o[i][5] * inv,
                                         o[i][6] * inv, o[i][7] * inv);
    }
}

// ---------------------------------------------------------------------------
// Launch
// ---------------------------------------------------------------------------
extern "C" void kernel_launch(void* const* d_in, const int* in_sizes, int n_in,
                              void* d_out, int out_size)
{
    const float* x     = (const float*)d_in[0];
    const float* Wq    = (const float*)d_in[1];
    const float* bq    = (const float*)d_in[2];
    const float* Wk    = (const float*)d_in[3];
    const float* bk    = (const float*)d_in[4];
    const float* Wv    = (const float*)d_in[5];
    const float* bv    = (const float*)d_in[6];
    const float* Wo    = (const float*)d_in[7];
    const float* bo    = (const float*)d_in[8];
    const float* ascl  = (const float*)d_in[9];
    float* out = (float*)d_out;

    float *q, *k, *v, *attn;
    cudaGetSymbolAddress((void**)&q,    g_q);
    cudaGetSymbolAddress((void**)&k,    g_k);
    cudaGetSymbolAddress((void**)&v,    g_v);
    cudaGetSymbolAddress((void**)&attn, g_attn);

    // Fused QKV projections: 24 x 64 CTAs
    dim3 qkvGrid(24, MTOT / BM);
    gemm_qkv<<<qkvGrid, 256>>>(x, Wq, Wk, Wv, bq, bk, bv, q, k, v);

    // Attention
    const int smem_bytes = (HD * LDQ + HD * LDK + HD * LDVV + AQT * LDP)
                           * (int)sizeof(float);   // 103,424 B
    cudaFuncSetAttribute(attn_kernel,
                         cudaFuncAttributeMaxDynamicSharedMemorySize, smem_bytes);
    dim3 agrid(Tlen / AQT, NHEADS, Bsz);  // (8, 16, 8)
    attn_kernel<<<agrid, 256, smem_bytes>>>(q, k, v, ascl, attn);

    // Output projection
    dim3 ggrid(EMB / BN, MTOT / BM);   // (8, 64)
    gemm_nt_bias<<<ggrid, 256>>>(attn, Wo, bo, out);
}

// round 12
// speedup vs baseline: 1.3299x; 1.3299x over previous
#include <cuda_runtime.h>
#include <cuda_bf16.h>
#include <math.h>
#include <stdint.h>

// Problem constants
#define Bsz    8
#define Tlen   1024
#define EMB    1024
#define NHEADS 16
#define HD     64
#define CHUNK  64

#define MTOT (Bsz * Tlen)          // 8192 rows

// ---------------------------------------------------------------------------
// Scratch (device globals — allocation-free per harness rules)
// ---------------------------------------------------------------------------
__device__ float g_q[MTOT * EMB];
__device__ float g_k[MTOT * EMB];
__device__ float g_v[MTOT * EMB];
__device__ float g_attn[MTOT * EMB];

// bf16 split operands
__device__ __nv_bfloat16 g_xh[MTOT * EMB];
__device__ __nv_bfloat16 g_xl[MTOT * EMB];
__device__ __nv_bfloat16 g_ah[MTOT * EMB];   // attn output split
__device__ __nv_bfloat16 g_al[MTOT * EMB];
__device__ __nv_bfloat16 g_wqh[EMB * EMB], g_wql[EMB * EMB];
__device__ __nv_bfloat16 g_wkh[EMB * EMB], g_wkl[EMB * EMB];
__device__ __nv_bfloat16 g_wvh[EMB * EMB], g_wvl[EMB * EMB];
__device__ __nv_bfloat16 g_woh[EMB * EMB], g_wol[EMB * EMB];

// ---------------------------------------------------------------------------
// Warp MMA helpers (mma.sync + ldmatrix — plain sm_103, no 'a' features)
// ---------------------------------------------------------------------------
__device__ __forceinline__ uint32_t smem_u32(const void* p) {
    uint32_t a;
    asm("{ .reg .u64 t; cvta.to.shared.u64 t, %1; cvt.u32.u64 %0, t; }"
        : "=r"(a) : "l"(p));
    return a;
}

__device__ __forceinline__ void ldsm_x4(uint32_t& r0, uint32_t& r1,
                                        uint32_t& r2, uint32_t& r3, uint32_t a) {
    asm volatile("ldmatrix.sync.aligned.m8n8.x4.shared.b16 {%0,%1,%2,%3}, [%4];"
                 : "=r"(r0), "=r"(r1), "=r"(r2), "=r"(r3) : "r"(a));
}
__device__ __forceinline__ void ldsm_x2(uint32_t& r0, uint32_t& r1, uint32_t a) {
    asm volatile("ldmatrix.sync.aligned.m8n8.x2.shared.b16 {%0,%1}, [%2];"
                 : "=r"(r0), "=r"(r1) : "r"(a));
}

__device__ __forceinline__ void mma16816(float* c, const uint32_t* a,
                                         const uint32_t* b) {
    asm volatile(
        "mma.sync.aligned.m16n8k16.row.col.f32.bf16.bf16.f32 "
        "{%0,%1,%2,%3}, {%4,%5,%6,%7}, {%8,%9}, {%0,%1,%2,%3};"
        : "+f"(c[0]), "+f"(c[1]), "+f"(c[2]), "+f"(c[3])
        : "r"(a[0]), "r"(a[1]), "r"(a[2]), "r"(a[3]), "r"(b[0]), "r"(b[1]));
}

// ---------------------------------------------------------------------------
// fp32 -> bf16 hi/lo split (elementwise)
// ---------------------------------------------------------------------------
__global__ __launch_bounds__(256)
void cvt_split(const float* __restrict__ s, __nv_bfloat16* __restrict__ h,
               __nv_bfloat16* __restrict__ l, int n)
{
    int i = (blockIdx.x * 256 + threadIdx.x) * 4;
    if (i >= n) return;
    float4 v = *(const float4*)(s + i);
    float vv[4] = {v.x, v.y, v.z, v.w};
#pragma unroll
    for (int t = 0; t < 4; t++) {
        __nv_bfloat16 hb = __float2bfloat16(vv[t]);
        float res = vv[t] - __bfloat162float(hb);
        h[i + t] = hb;
        l[i + t] = __float2bfloat16(res);
    }
}

// ---------------------------------------------------------------------------
// bf16-split tensor GEMM: C[128,128] tile of A[M,1024]*B[N,1024]^T + bias.
// C = Ah*Bh + Ah*Bl + Al*Bh, fp32 accumulation (mma.sync m16n8k16).
// 256 threads = 8 warps (2m x 4n); warp tile 64x32; K chunk 32.
// Smem tiles: 128 rows x (32+8 pad) bf16, 80B row stride (ldmatrix
// conflict-free, 16B-aligned rows). Double-buffered, reg-prefetch, 1 sync/chunk.
// ---------------------------------------------------------------------------
#define TCK   32                    // bf16 k per chunk
#define NCHK  (EMB / TCK)           // 32 chunks
#define TLD   40                    // padded row length in bf16 (80 B)
#define TILE_B (128 * TLD * 2)      // 10240 B per operand tile
#define BUF_B  (4 * TILE_B)         // Ah, Al, Bh, Bl
#define SMEM_MMA (2 * BUF_B)        // 81920 B

__device__ __forceinline__
void ld_chunk(uint4* v,
              const __nv_bfloat16* Ah0, const __nv_bfloat16* Al0,
              const __nv_bfloat16* Bh0, const __nv_bfloat16* Bl0,
              int row, int col, int kc)
{
    const size_t off = (size_t)row * EMB + kc + col;
    v[0] = *(const uint4*)(Ah0 + off); v[1] = *(const uint4*)(Ah0 + off + 8);
    v[2] = *(const uint4*)(Al0 + off); v[3] = *(const uint4*)(Al0 + off + 8);
    v[4] = *(const uint4*)(Bh0 + off); v[5] = *(const uint4*)(Bh0 + off + 8);
    v[6] = *(const uint4*)(Bl0 + off); v[7] = *(const uint4*)(Bl0 + off + 8);
}

__device__ __forceinline__
void st_chunk(char* smbuf, const uint4* v, int row, int col)
{
    const uint32_t off = (uint32_t)(row * TLD + col) * 2;
    *(uint4*)(smbuf + 0 * TILE_B + off)      = v[0];
    *(uint4*)(smbuf + 0 * TILE_B + off + 16) = v[1];
    *(uint4*)(smbuf + 1 * TILE_B + off)      = v[2];
    *(uint4*)(smbuf + 1 * TILE_B + off + 16) = v[3];
    *(uint4*)(smbuf + 2 * TILE_B + off)      = v[4];
    *(uint4*)(smbuf + 2 * TILE_B + off + 16) = v[5];
    *(uint4*)(smbuf + 3 * TILE_B + off)      = v[6];
    *(uint4*)(smbuf + 3 * TILE_B + off + 16) = v[7];
}

__device__ __forceinline__
void gemm_mma_body(const __nv_bfloat16* __restrict__ ah, const __nv_bfloat16* __restrict__ al,
                   const __nv_bfloat16* __restrict__ bh, const __nv_bfloat16* __restrict__ bl,
                   const float* __restrict__ bias, float* __restrict__ C,
                   int mBase, int nBase)
{
    extern __shared__ char sm[];
    const uint32_t smb = smem_u32(sm);

    const int tid  = threadIdx.x;
    const int wid  = tid >> 5;
    const int lane = tid & 31;
    const int wm = (wid >> 2) * 64;     // warp m offset (0/64)
    const int wn = (wid & 3) * 32;      // warp n offset (0/32/64/96)

    // global loader mapping: row 0..127, 16-bf16 half
    const int grow = tid >> 1;
    const int gcol = (tid & 1) * 16;

    const __nv_bfloat16* Ah0 = ah + (size_t)mBase * EMB;
    const __nv_bfloat16* Al0 = al + (size_t)mBase * EMB;
    const __nv_bfloat16* Bh0 = bh + (size_t)nBase * EMB;
    const __nv_bfloat16* Bl0 = bl + (size_t)nBase * EMB;

    // ldmatrix per-lane address pieces (in bf16 elements)
    const uint32_t aRow = wm + (lane & 15);
    const uint32_t aK   = (lane >> 4) * 8;
    const uint32_t bRow = wn + (lane & 7);
    const uint32_t bK   = ((lane >> 3) & 1) * 8;

    float acc[4][4][4];
#pragma unroll
    for (int mi = 0; mi < 4; mi++)
#pragma unroll
        for (int ni = 0; ni < 4; ni++)
#pragma unroll
            for (int e = 0; e < 4; e++) acc[mi][ni][e] = 0.f;

    // preload chunk 0 into buffer 0
    {
        uint4 v[8];
        ld_chunk(v, Ah0, Al0, Bh0, Bl0, grow, gcol, 0);
        st_chunk(sm, v, grow, gcol);
    }
    __syncthreads();

    int buf = 0;
    for (int c = 0; c < NCHK; c++) {
        const bool more = (c + 1) < NCHK;
        uint4 pf[8];
        if (more) ld_chunk(pf, Ah0, Al0, Bh0, Bl0, grow, gcol, (c + 1) * TCK);

        const uint32_t bb = smb + buf * BUF_B;
#pragma unroll
        for (int k16 = 0; k16 < 2; k16++) {
            const uint32_t kb = k16 * 16;
            uint32_t fah[4][4], fal[4][4], fbh[4][2], fbl[4][2];
#pragma unroll
            for (int mi = 0; mi < 4; mi++) {
                uint32_t ao = ((aRow + mi * 16) * TLD + kb + aK) * 2;
                ldsm_x4(fah[mi][0], fah[mi][1], fah[mi][2], fah[mi][3],
                        bb + 0 * TILE_B + ao);
                ldsm_x4(fal[mi][0], fal[mi][1], fal[mi][2], fal[mi][3],
                        bb + 1 * TILE_B + ao);
            }
#pragma unroll
            for (int ni = 0; ni < 4; ni++) {
                uint32_t bo = ((bRow + ni * 8) * TLD + kb + bK) * 2;
                ldsm_x2(fbh[ni][0], fbh[ni][1], bb + 2 * TILE_B + bo);
                ldsm_x2(fbl[ni][0], fbl[ni][1], bb + 3 * TILE_B + bo);
            }
#pragma unroll
            for (int mi = 0; mi < 4; mi++)
#pragma unroll
                for (int ni = 0; ni < 4; ni++) {
                    mma16816(acc[mi][ni], fah[mi], fbh[ni]);
                    mma16816(acc[mi][ni], fah[mi], fbl[ni]);
                    mma16816(acc[mi][ni], fal[mi], fbh[ni]);
                }
        }

        if (more) {
            const int nb = buf ^ 1;
            st_chunk(sm + nb * BUF_B, pf, grow, gcol);
            __syncthreads();
            buf = nb;
        }
    }

    // epilogue: c0,c1 -> (m = tr, n = tc,tc+1); c2,c3 -> (m = tr+8)
    const int tr = lane >> 2;
    const int tc = (lane & 3) * 2;
#pragma unroll
    for (int mi = 0; mi < 4; mi++) {
        const int gm0 = mBase + wm + mi * 16 + tr;
#pragma unroll
        for (int ni = 0; ni < 4; ni++) {
            const int gn = nBase + wn + ni * 8 + tc;
            const float b0 = bias[gn], b1 = bias[gn + 1];
            float2 lo = make_float2(acc[mi][ni][0] + b0, acc[mi][ni][1] + b1);
            float2 hi = make_float2(acc[mi][ni][2] + b0, acc[mi][ni][3] + b1);
            *(float2*)(C + (size_t)gm0 * EMB + gn)       = lo;
            *(float2*)(C + (size_t)(gm0 + 8) * EMB + gn) = hi;
        }
    }
}

// Fused QKV: grid (24, 64) = (3 mats x 8 n-tiles, 64 m-tiles)
__global__ __launch_bounds__(256)
void gemm_qkv_tc(const __nv_bfloat16* __restrict__ xh, const __nv_bfloat16* __restrict__ xl,
                 const __nv_bfloat16* __restrict__ wqh, const __nv_bfloat16* __restrict__ wql,
                 const __nv_bfloat16* __restrict__ wkh, const __nv_bfloat16* __restrict__ wkl,
                 const __nv_bfloat16* __restrict__ wvh, const __nv_bfloat16* __restrict__ wvl,
                 const float* __restrict__ bq, const float* __restrict__ bk,
                 const float* __restrict__ bv,
                 float* __restrict__ q, float* __restrict__ k, float* __restrict__ v)
{
    const int sel = blockIdx.x >> 3;
    const int nb  = blockIdx.x & 7;
    const __nv_bfloat16* wh = (sel == 0) ? wqh : (sel == 1) ? wkh : wvh;
    const __nv_bfloat16* wl = (sel == 0) ? wql : (sel == 1) ? wkl : wvl;
    const float* bias       = (sel == 0) ? bq  : (sel == 1) ? bk  : bv;
    float* C                = (sel == 0) ? q   : (sel == 1) ? k   : v;
    gemm_mma_body(xh, xl, wh, wl, bias, C, blockIdx.y * 128, nb * 128);
}

// Output projection: grid (8, 64)
__global__ __launch_bounds__(256)
void gemm_o_tc(const __nv_bfloat16* __restrict__ ah, const __nv_bfloat16* __restrict__ al,
               const __nv_bfloat16* __restrict__ wh, const __nv_bfloat16* __restrict__ wl,
               const float* __restrict__ bias, float* __restrict__ C)
{
    gemm_mma_body(ah, al, wh, wl, bias, C, blockIdx.y * 128, blockIdx.x * 128);
}

// ---------------------------------------------------------------------------
// Fused attention, flash-style (verified R10 version, unchanged).
// 128q x 64k tile, 256 threads = 32 ty x 8 tx.
// ---------------------------------------------------------------------------
#define AQT 128
#define AKT 64
#define LDQ 132
#define LDK 68
#define LDVV 68
#define LDP 68

__global__ __launch_bounds__(256, 2)
void attn_kernel(const float* __restrict__ Q, const float* __restrict__ K,
                 const float* __restrict__ V, const float* __restrict__ scale_p,
                 float* __restrict__ O)
{
    extern __shared__ float smem[];
    float (*Qs)[LDQ]  = (float(*)[LDQ]) (smem);
    float (*Ks)[LDK]  = (float(*)[LDK]) (smem + HD * LDQ);
    float (*Vs)[LDVV] = (float(*)[LDVV])(smem + HD * LDQ + HD * LDK);
    float (*Ps)[LDP]  = (float(*)[LDP]) (smem + HD * LDQ + HD * (LDK + LDVV));

    const int tid = threadIdx.x;
    const int tx  = tid & 7;
    const int ty  = tid >> 3;
    const int qt = blockIdx.x, h = blockIdx.y, b = blockIdx.z;
    const float scale = scale_p[0];

    {
        const int r = tid >> 1;
        const int c = (tid & 1) * 32;
        const float* Qb = Q + ((size_t)b * Tlen + qt * AQT + r) * EMB + h * HD + c;
#pragma unroll
        for (int j = 0; j < 8; j++) {
            float4 q4 = *(const float4*)(Qb + 4 * j);
            Qs[c + 4 * j + 0][r] = q4.x * scale;
            Qs[c + 4 * j + 1][r] = q4.y * scale;
            Qs[c + 4 * j + 2][r] = q4.z * scale;
            Qs[c + 4 * j + 3][r] = q4.w * scale;
        }
    }

    float m[4], l[4], o[4][8];
#pragma unroll
    for (int i = 0; i < 4; i++) {
        m[i] = -INFINITY; l[i] = 0.f;
#pragma unroll
        for (int j = 0; j < 8; j++) o[i][j] = 0.f;
    }

    const int r2 = tid >> 2;
    const int c2 = (tid & 3) * 16;

    for (int kt = 0; kt < Tlen / AKT; kt++) {
        __syncthreads();
        {
            const float* Kb = K + ((size_t)b * Tlen + kt * AKT + r2) * EMB + h * HD + c2;
            const float* Vb = V + ((size_t)b * Tlen + kt * AKT + r2) * EMB + h * HD + c2;
#pragma unroll
            for (int j = 0; j < 4; j++) {
                float4 k4 = *(const float4*)(Kb + 4 * j);
                Ks[c2 + 4 * j + 0][r2] = k4.x;
                Ks[c2 + 4 * j + 1][r2] = k4.y;
                Ks[c2 + 4 * j + 2][r2] = k4.z;
                Ks[c2 + 4 * j + 3][r2] = k4.w;
                *(float4*)&Vs[r2][c2 + 4 * j] = *(const float4*)(Vb + 4 * j);
            }
        }
        __syncthreads();

        float s[4][8];
#pragma unroll
        for (int i = 0; i < 4; i++)
#pragma unroll
            for (int j = 0; j < 8; j++) s[i][j] = 0.f;

#pragma unroll 4
        for (int d = 0; d < HD; d++) {
            float4 qv = *(const float4*)&Qs[d][ty * 4];
            float4 kL = *(const float4*)&Ks[d][tx * 8];
            float4 kH = *(const float4*)&Ks[d][tx * 8 + 4];
            float qa[4] = {qv.x, qv.y, qv.z, qv.w};
            float kb8[8] = {kL.x, kL.y, kL.z, kL.w, kH.x, kH.y, kH.z, kH.w};
#pragma unroll
            for (int i = 0; i < 4; i++)
#pragma unroll
                for (int j = 0; j < 8; j++)
                    s[i][j] = fmaf(qa[i], kb8[j], s[i][j]);
        }

#pragma unroll
        for (int i = 0; i < 4; i++) {
            const int qr = ty * 4 + i;
            if (kt == qt * 2 + (qr >> 6)) {
                const int rel = qr & 63;
#pragma unroll
                for (int j = 0; j < 8; j++)
                    if (tx * 8 + j > rel) s[i][j] = -INFINITY;
            }
        }

#pragma unroll
        for (int i = 0; i < 4; i++) {
            float tm = fmaxf(fmaxf(fmaxf(s[i][0], s[i][1]), fmaxf(s[i][2], s[i][3])),
                             fmaxf(fmaxf(s[i][4], s[i][5]), fmaxf(s[i][6], s[i][7])));
            tm = fmaxf(tm, __shfl_xor_sync(0xffffffffu, tm, 1));
            tm = fmaxf(tm, __shfl_xor_sync(0xffffffffu, tm, 2));
            tm = fmaxf(tm, __shfl_xor_sync(0xffffffffu, tm, 4));
            float mnew = fmaxf(m[i], tm);
            float corr = __expf(m[i] - mnew);

            float p[8];
            float ts = 0.f;
#pragma unroll
            for (int j = 0; j < 8; j++) {
                p[j] = __expf(s[i][j] - mnew);
                ts += p[j];
            }
            ts += __shfl_xor_sync(0xffffffffu, ts, 1);
            ts += __shfl_xor_sync(0xffffffffu, ts, 2);
            ts += __shfl_xor_sync(0xffffffffu, ts, 4);
            l[i] = l[i] * corr + ts;
            m[i] = mnew;
#pragma unroll
            for (int j = 0; j < 8; j++) o[i][j] *= corr;
            *(float4*)&Ps[ty * 4 + i][tx * 8]     = make_float4(p[0], p[1], p[2], p[3]);
            *(float4*)&Ps[ty * 4 + i][tx * 8 + 4] = make_float4(p[4], p[5], p[6], p[7]);
        }
        __syncwarp();

#pragma unroll 2
        for (int kk = 0; kk < AKT; kk += 4) {
            float4 v0L = *(const float4*)&Vs[kk + 0][tx * 8];
            float4 v0H = *(const float4*)&Vs[kk + 0][tx * 8 + 4];
            float4 v1L = *(const float4*)&Vs[kk + 1][tx * 8];
            float4 v1H = *(const float4*)&Vs[kk + 1][tx * 8 + 4];
            float4 v2L = *(const float4*)&Vs[kk + 2][tx * 8];
            float4 v2H = *(const float4*)&Vs[kk + 2][tx * 8 + 4];
            float4 v3L = *(const float4*)&Vs[kk + 3][tx * 8];
            float4 v3H = *(const float4*)&Vs[kk + 3][tx * 8 + 4];
            float vb[4][8] = {
                {v0L.x, v0L.y, v0L.z, v0L.w, v0H.x, v0H.y, v0H.z, v0H.w},
                {v1L.x, v1L.y, v1L.z, v1L.w, v1H.x, v1H.y, v1H.z, v1H.w},
                {v2L.x, v2L.y, v2L.z, v2L.w, v2H.x, v2H.y, v2H.z, v2H.w},
                {v3L.x, v3L.y, v3L.z, v3L.w, v3H.x, v3H.y, v3H.z, v3H.w},
            };
#pragma unroll
            for (int i = 0; i < 4; i++) {
                float4 pr = *(const float4*)&Ps[ty * 4 + i][kk];
                float pa[4] = {pr.x, pr.y, pr.z, pr.w};
#pragma unroll
                for (int t = 0; t < 4; t++)
#pragma unroll
                    for (int j = 0; j < 8; j++)
                        o[i][j] = fmaf(pa[t], vb[t][j], o[i][j]);
            }
        }
    }

#pragma unroll
    for (int i = 0; i < 4; i++) {
        float inv = 1.f / l[i];
        float* Ob = O + ((size_t)b * Tlen + qt * AQT + ty * 4 + i) * EMB
                      + h * HD + tx * 8;
        *(float4*)Ob       = make_float4(o[i][0] * inv, o[i][1] * inv,
                                         o[i][2] * inv, o[i][3] * inv);
        *(float4*)(Ob + 4) = make_float4(o[i][4] * inv, o[i][5] * inv,
                                         o[i][6] * inv, o[i][7] * inv);
    }
}

// ---------------------------------------------------------------------------
// Launch
// ---------------------------------------------------------------------------
extern "C" void kernel_launch(void* const* d_in, const int* in_sizes, int n_in,
                              void* d_out, int out_size)
{
    const float* x     = (const float*)d_in[0];
    const float* Wq    = (const float*)d_in[1];
    const float* bq    = (const float*)d_in[2];
    const float* Wk    = (const float*)d_in[3];
    const float* bk    = (const float*)d_in[4];
    const float* Wv    = (const float*)d_in[5];
    const float* bv    = (const float*)d_in[6];
    const float* Wo    = (const float*)d_in[7];
    const float* bo    = (const float*)d_in[8];
    const float* ascl  = (const float*)d_in[9];
    float* out = (float*)d_out;

    float *q, *k, *v, *attn;
    cudaGetSymbolAddress((void**)&q,    g_q);
    cudaGetSymbolAddress((void**)&k,    g_k);
    cudaGetSymbolAddress((void**)&v,    g_v);
    cudaGetSymbolAddress((void**)&attn, g_attn);

    __nv_bfloat16 *xh, *xl, *ah, *al;
    __nv_bfloat16 *wqh, *wql, *wkh, *wkl, *wvh, *wvl, *woh, *wol;
    cudaGetSymbolAddress((void**)&xh, g_xh);   cudaGetSymbolAddress((void**)&xl, g_xl);
    cudaGetSymbolAddress((void**)&ah, g_ah);   cudaGetSymbolAddress((void**)&al, g_al);
    cudaGetSymbolAddress((void**)&wqh, g_wqh); cudaGetSymbolAddress((void**)&wql, g_wql);
    cudaGetSymbolAddress((void**)&wkh, g_wkh); cudaGetSymbolAddress((void**)&wkl, g_wkl);
    cudaGetSymbolAddress((void**)&wvh, g_wvh); cudaGetSymbolAddress((void**)&wvl, g_wvl);
    cudaGetSymbolAddress((void**)&woh, g_woh); cudaGetSymbolAddress((void**)&wol, g_wol);

    // bf16 hi/lo splits
    const int nX = MTOT * EMB;     // 8M
    const int nW = EMB * EMB;      // 1M
    cvt_split<<<nX / 1024, 256>>>(x,  xh,  xl,  nX);
    cvt_split<<<nW / 1024, 256>>>(Wq, wqh, wql, nW);
    cvt_split<<<nW / 1024, 256>>>(Wk, wkh, wkl, nW);
    cvt_split<<<nW / 1024, 256>>>(Wv, wvh, wvl, nW);
    cvt_split<<<nW / 1024, 256>>>(Wo, woh, wol, nW);

    cudaFuncSetAttribute(gemm_qkv_tc, cudaFuncAttributeMaxDynamicSharedMemorySize, SMEM_MMA);
    cudaFuncSetAttribute(gemm_o_tc,   cudaFuncAttributeMaxDynamicSharedMemorySize, SMEM_MMA);

    // QKV projections on tensor cores (mma.sync): grid (24, 64)
    dim3 qkvGrid(24, MTOT / 128);
    gemm_qkv_tc<<<qkvGrid, 256, SMEM_MMA>>>(xh, xl, wqh, wql, wkh, wkl, wvh, wvl,
                                            bq, bk, bv, q, k, v);

    // Attention (fp32 SIMT, verified)
    const int asmem = (HD * LDQ + HD * LDK + HD * LDVV + AQT * LDP) * (int)sizeof(float);
    cudaFuncSetAttribute(attn_kernel, cudaFuncAttributeMaxDynamicSharedMemorySize, asmem);
    dim3 agrid(Tlen / AQT, NHEADS, Bsz);
    attn_kernel<<<agrid, 256, asmem>>>(q, k, v, ascl, attn);

    // split attention output, then output projection on tensor cores
    cvt_split<<<nX / 1024, 256>>>(attn, ah, al, nX);
    dim3 ogrid(EMB / 128, MTOT / 128);
    gemm_o_tc<<<ogrid, 256, SMEM_MMA>>>(ah, al, woh, wol, bo, out);
}

// round 13
// speedup vs baseline: 2.1982x; 1.6529x over previous
#include <cuda_runtime.h>
#include <cuda_bf16.h>
#include <math.h>
#include <stdint.h>

// Problem constants
#define Bsz    8
#define Tlen   1024
#define EMB    1024
#define NHEADS 16
#define HD     64

#define MTOT (Bsz * Tlen)          // 8192 rows

// ---------------------------------------------------------------------------
// Scratch (device globals — allocation-free per harness rules). All bf16
// hi/lo split pairs; no fp32 intermediates anywhere.
// ---------------------------------------------------------------------------
__device__ __nv_bfloat16 g_xh[MTOT * EMB], g_xl[MTOT * EMB];
__device__ __nv_bfloat16 g_qh[MTOT * EMB], g_ql[MTOT * EMB];
__device__ __nv_bfloat16 g_kh[MTOT * EMB], g_kl[MTOT * EMB];
__device__ __nv_bfloat16 g_vh[MTOT * EMB], g_vl[MTOT * EMB];
__device__ __nv_bfloat16 g_ah[MTOT * EMB], g_al[MTOT * EMB];
__device__ __nv_bfloat16 g_wqh[EMB * EMB], g_wql[EMB * EMB];
__device__ __nv_bfloat16 g_wkh[EMB * EMB], g_wkl[EMB * EMB];
__device__ __nv_bfloat16 g_wvh[EMB * EMB], g_wvl[EMB * EMB];
__device__ __nv_bfloat16 g_woh[EMB * EMB], g_wol[EMB * EMB];

// ---------------------------------------------------------------------------
// Warp MMA helpers (mma.sync + ldmatrix — plain sm_103 features only)
// ---------------------------------------------------------------------------
__device__ __forceinline__ uint32_t smem_u32(const void* p) {
    uint32_t a;
    asm("{ .reg .u64 t; cvta.to.shared.u64 t, %1; cvt.u32.u64 %0, t; }"
        : "=r"(a) : "l"(p));
    return a;
}

__device__ __forceinline__ void ldsm_x4(uint32_t& r0, uint32_t& r1,
                                        uint32_t& r2, uint32_t& r3, uint32_t a) {
    asm volatile("ldmatrix.sync.aligned.m8n8.x4.shared.b16 {%0,%1,%2,%3}, [%4];"
                 : "=r"(r0), "=r"(r1), "=r"(r2), "=r"(r3) : "r"(a));
}
__device__ __forceinline__ void ldsm_x4_t(uint32_t* r, uint32_t a) {
    asm volatile("ldmatrix.sync.aligned.m8n8.x4.trans.shared.b16 {%0,%1,%2,%3}, [%4];"
                 : "=r"(r[0]), "=r"(r[1]), "=r"(r[2]), "=r"(r[3]) : "r"(a));
}
__device__ __forceinline__ void ldsm_x2(uint32_t& r0, uint32_t& r1, uint32_t a) {
    asm volatile("ldmatrix.sync.aligned.m8n8.x2.shared.b16 {%0,%1}, [%2];"
                 : "=r"(r0), "=r"(r1) : "r"(a));
}

__device__ __forceinline__ void mma16816(float* c, const uint32_t* a,
                                         const uint32_t* b) {
    asm volatile(
        "mma.sync.aligned.m16n8k16.row.col.f32.bf16.bf16.f32 "
        "{%0,%1,%2,%3}, {%4,%5,%6,%7}, {%8,%9}, {%0,%1,%2,%3};"
        : "+f"(c[0]), "+f"(c[1]), "+f"(c[2]), "+f"(c[3])
        : "r"(a[0]), "r"(a[1]), "r"(a[2]), "r"(a[3]), "r"(b[0]), "r"(b[1]));
}

// split a,b (fp32) into packed bf16 hi/lo pair registers ({lo-halfword=a})
__device__ __forceinline__ void pack_pair(float a, float b,
                                          uint32_t& hreg, uint32_t& lreg) {
    __nv_bfloat16 ha = __float2bfloat16(a);
    __nv_bfloat16 hb = __float2bfloat16(b);
    __nv_bfloat162 hp; hp.x = ha; hp.y = hb;
    hreg = *(uint32_t*)&hp;
    __nv_bfloat162 lp;
    lp.x = __float2bfloat16(a - __bfloat162float(ha));
    lp.y = __float2bfloat16(b - __bfloat162float(hb));
    lreg = *(uint32_t*)&lp;
}

__device__ __forceinline__ void split_store(__nv_bfloat16* h, __nv_bfloat16* l,
                                            size_t idx, float a, float b) {
    __nv_bfloat16 ha = __float2bfloat16(a);
    __nv_bfloat16 hb = __float2bfloat16(b);
    __nv_bfloat162 hp; hp.x = ha; hp.y = hb;
    *(__nv_bfloat162*)(h + idx) = hp;
    __nv_bfloat162 lp;
    lp.x = __float2bfloat16(a - __bfloat162float(ha));
    lp.y = __float2bfloat16(b - __bfloat162float(hb));
    *(__nv_bfloat162*)(l + idx) = lp;
}

// ---------------------------------------------------------------------------
// fp32 -> bf16 hi/lo split (elementwise)
// ---------------------------------------------------------------------------
__global__ __launch_bounds__(256)
void cvt_split(const float* __restrict__ s, __nv_bfloat16* __restrict__ h,
               __nv_bfloat16* __restrict__ l, int n)
{
    int i = (blockIdx.x * 256 + threadIdx.x) * 4;
    if (i >= n) return;
    float4 v = *(const float4*)(s + i);
    float vv[4] = {v.x, v.y, v.z, v.w};
#pragma unroll
    for (int t = 0; t < 4; t++) {
        __nv_bfloat16 hb = __float2bfloat16(vv[t]);
        h[i + t] = hb;
        l[i + t] = __float2bfloat16(vv[t] - __bfloat162float(hb));
    }
}

// ---------------------------------------------------------------------------
// bf16-split tensor GEMM (verified R12 core): C tile 128x128 of
// A[M,1024]*B[N,1024]^T + bias;  C = Ah*Bh + Ah*Bl + Al*Bh, fp32 accum.
// SPLIT=true: epilogue writes bf16 hi/lo pair; else fp32.
// ---------------------------------------------------------------------------
#define TCK   32
#define NCHK  (EMB / TCK)
#define TLD   40
#define TILE_B (128 * TLD * 2)
#define BUF_B  (4 * TILE_B)
#define SMEM_MMA (2 * BUF_B)        // 81920 B

__device__ __forceinline__
void ld_chunk(uint4* v,
              const __nv_bfloat16* Ah0, const __nv_bfloat16* Al0,
              const __nv_bfloat16* Bh0, const __nv_bfloat16* Bl0,
              int row, int col, int kc)
{
    const size_t off = (size_t)row * EMB + kc + col;
    v[0] = *(const uint4*)(Ah0 + off); v[1] = *(const uint4*)(Ah0 + off + 8);
    v[2] = *(const uint4*)(Al0 + off); v[3] = *(const uint4*)(Al0 + off + 8);
    v[4] = *(const uint4*)(Bh0 + off); v[5] = *(const uint4*)(Bh0 + off + 8);
    v[6] = *(const uint4*)(Bl0 + off); v[7] = *(const uint4*)(Bl0 + off + 8);
}

__device__ __forceinline__
void st_chunk(char* smbuf, const uint4* v, int row, int col)
{
    const uint32_t off = (uint32_t)(row * TLD + col) * 2;
    *(uint4*)(smbuf + 0 * TILE_B + off)      = v[0];
    *(uint4*)(smbuf + 0 * TILE_B + off + 16) = v[1];
    *(uint4*)(smbuf + 1 * TILE_B + off)      = v[2];
    *(uint4*)(smbuf + 1 * TILE_B + off + 16) = v[3];
    *(uint4*)(smbuf + 2 * TILE_B + off)      = v[4];
    *(uint4*)(smbuf + 2 * TILE_B + off + 16) = v[5];
    *(uint4*)(smbuf + 3 * TILE_B + off)      = v[6];
    *(uint4*)(smbuf + 3 * TILE_B + off + 16) = v[7];
}

template <bool SPLIT>
__device__ __forceinline__
void gemm_mma_body(const __nv_bfloat16* __restrict__ ah, const __nv_bfloat16* __restrict__ al,
                   const __nv_bfloat16* __restrict__ bh, const __nv_bfloat16* __restrict__ bl,
                   const float* __restrict__ bias,
                   float* __restrict__ C,
                   __nv_bfloat16* __restrict__ Ch, __nv_bfloat16* __restrict__ Cl,
                   int mBase, int nBase)
{
    extern __shared__ char sm[];
    const uint32_t smb = smem_u32(sm);

    const int tid  = threadIdx.x;
    const int wid  = tid >> 5;
    const int lane = tid & 31;
    const int wm = (wid >> 2) * 64;
    const int wn = (wid & 3) * 32;

    const int grow = tid >> 1;
    const int gcol = (tid & 1) * 16;

    const __nv_bfloat16* Ah0 = ah + (size_t)mBase * EMB;
    const __nv_bfloat16* Al0 = al + (size_t)mBase * EMB;
    const __nv_bfloat16* Bh0 = bh + (size_t)nBase * EMB;
    const __nv_bfloat16* Bl0 = bl + (size_t)nBase * EMB;

    const uint32_t aRow = wm + (lane & 15);
    const uint32_t aK   = (lane >> 4) * 8;
    const uint32_t bRow = wn + (lane & 7);
    const uint32_t bK   = ((lane >> 3) & 1) * 8;

    float acc[4][4][4];
#pragma unroll
    for (int mi = 0; mi < 4; mi++)
#pragma unroll
        for (int ni = 0; ni < 4; ni++)
#pragma unroll
            for (int e = 0; e < 4; e++) acc[mi][ni][e] = 0.f;

    {
        uint4 v[8];
        ld_chunk(v, Ah0, Al0, Bh0, Bl0, grow, gcol, 0);
        st_chunk(sm, v, grow, gcol);
    }
    __syncthreads();

    int buf = 0;
    for (int c = 0; c < NCHK; c++) {
        const bool more = (c + 1) < NCHK;
        uint4 pf[8];
        if (more) ld_chunk(pf, Ah0, Al0, Bh0, Bl0, grow, gcol, (c + 1) * TCK);

        const uint32_t bb = smb + buf * BUF_B;
#pragma unroll
        for (int k16 = 0; k16 < 2; k16++) {
            const uint32_t kb = k16 * 16;
            uint32_t fah[4][4], fal[4][4], fbh[4][2], fbl[4][2];
#pragma unroll
            for (int mi = 0; mi < 4; mi++) {
                uint32_t ao = ((aRow + mi * 16) * TLD + kb + aK) * 2;
                ldsm_x4(fah[mi][0], fah[mi][1], fah[mi][2], fah[mi][3],
                        bb + 0 * TILE_B + ao);
                ldsm_x4(fal[mi][0], fal[mi][1], fal[mi][2], fal[mi][3],
                        bb + 1 * TILE_B + ao);
            }
#pragma unroll
            for (int ni = 0; ni < 4; ni++) {
                uint32_t bo = ((bRow + ni * 8) * TLD + kb + bK) * 2;
                ldsm_x2(fbh[ni][0], fbh[ni][1], bb + 2 * TILE_B + bo);
                ldsm_x2(fbl[ni][0], fbl[ni][1], bb + 3 * TILE_B + bo);
            }
#pragma unroll
            for (int mi = 0; mi < 4; mi++)
#pragma unroll
                for (int ni = 0; ni < 4; ni++) {
                    mma16816(acc[mi][ni], fah[mi], fbh[ni]);
                    mma16816(acc[mi][ni], fah[mi], fbl[ni]);
                    mma16816(acc[mi][ni], fal[mi], fbh[ni]);
                }
        }

        if (more) {
            const int nb = buf ^ 1;
            st_chunk(sm + nb * BUF_B, pf, grow, gcol);
            __syncthreads();
            buf = nb;
        }
    }

    const int tr = lane >> 2;
    const int tc = (lane & 3) * 2;
#pragma unroll
    for (int mi = 0; mi < 4; mi++) {
        const int gm0 = mBase + wm + mi * 16 + tr;
#pragma unroll
        for (int ni = 0; ni < 4; ni++) {
            const int gn = nBase + wn + ni * 8 + tc;
            const float b0 = bias[gn], b1 = bias[gn + 1];
            float v0 = acc[mi][ni][0] + b0, v1 = acc[mi][ni][1] + b1;
            float v2 = acc[mi][ni][2] + b0, v3 = acc[mi][ni][3] + b1;
            if (SPLIT) {
                split_store(Ch, Cl, (size_t)gm0 * EMB + gn, v0, v1);
                split_store(Ch, Cl, (size_t)(gm0 + 8) * EMB + gn, v2, v3);
            } else {
                *(float2*)(C + (size_t)gm0 * EMB + gn)       = make_float2(v0, v1);
                *(float2*)(C + (size_t)(gm0 + 8) * EMB + gn) = make_float2(v2, v3);
            }
        }
    }
}

// Fused QKV (split outputs): grid (24, 64)
__global__ __launch_bounds__(256)
void gemm_qkv_tc(const __nv_bfloat16* __restrict__ xh, const __nv_bfloat16* __restrict__ xl,
                 const __nv_bfloat16* __restrict__ wqh, const __nv_bfloat16* __restrict__ wql,
                 const __nv_bfloat16* __restrict__ wkh, const __nv_bfloat16* __restrict__ wkl,
                 const __nv_bfloat16* __restrict__ wvh, const __nv_bfloat16* __restrict__ wvl,
                 const float* __restrict__ bq, const float* __restrict__ bk,
                 const float* __restrict__ bv,
                 __nv_bfloat16* __restrict__ qh, __nv_bfloat16* __restrict__ ql,
                 __nv_bfloat16* __restrict__ kh, __nv_bfloat16* __restrict__ kl,
                 __nv_bfloat16* __restrict__ vh, __nv_bfloat16* __restrict__ vl)
{
    const int sel = blockIdx.x >> 3;
    const int nb  = blockIdx.x & 7;
    const __nv_bfloat16* wh = (sel == 0) ? wqh : (sel == 1) ? wkh : wvh;
    const __nv_bfloat16* wl = (sel == 0) ? wql : (sel == 1) ? wkl : wvl;
    const float* bias       = (sel == 0) ? bq  : (sel == 1) ? bk  : bv;
    __nv_bfloat16* Ch       = (sel == 0) ? qh  : (sel == 1) ? kh  : vh;
    __nv_bfloat16* Cl       = (sel == 0) ? ql  : (sel == 1) ? kl  : vl;
    gemm_mma_body<true>(xh, xl, wh, wl, bias, nullptr, Ch, Cl,
                        blockIdx.y * 128, nb * 128);
}

// Output projection (fp32 output): grid (8, 64)
__global__ __launch_bounds__(256)
void gemm_o_tc(const __nv_bfloat16* __restrict__ ah, const __nv_bfloat16* __restrict__ al,
               const __nv_bfloat16* __restrict__ wh, const __nv_bfloat16* __restrict__ wl,
               const float* __restrict__ bias, float* __restrict__ C)
{
    gemm_mma_body<false>(ah, al, wh, wl, bias, C, nullptr, nullptr,
                         blockIdx.y * 128, blockIdx.x * 128);
}

// ---------------------------------------------------------------------------
// Tensor-core flash attention (bf16 3-term split for S and PV, fp32 softmax).
// CTA = (q-tile 128, head, batch); 8 warps x 16 q-rows.
// Key tiles of 64; warp computes S 16x64 (8 n-tiles), softmax in frags,
// P repacked register-only into A-frags, PV with V via ldmatrix.trans.
// Mask: only the diagonal 64-chunk tile, upper-triangular.
// Output written directly as bf16 hi/lo split for the O-projection.
// ---------------------------------------------------------------------------
#define LDT 72                       // padded row (bf16 elements)
#define QH0 0
#define QL0 (128 * LDT)
#define KH0 (2 * 128 * LDT)
#define KL0 (KH0 + 64 * LDT)
#define VH0 (KH0 + 2 * 64 * LDT)
#define VL0 (KH0 + 3 * 64 * LDT)
#define ATT_SMEM ((2 * 128 * LDT + 4 * 64 * LDT) * 2)   // 73,728 B

__global__ __launch_bounds__(256)
void attn_mma(const __nv_bfloat16* __restrict__ qh, const __nv_bfloat16* __restrict__ ql,
              const __nv_bfloat16* __restrict__ kh, const __nv_bfloat16* __restrict__ kl,
              const __nv_bfloat16* __restrict__ vh, const __nv_bfloat16* __restrict__ vl,
              const float* __restrict__ scale_p,
              __nv_bfloat16* __restrict__ oh, __nv_bfloat16* __restrict__ ol)
{
    extern __shared__ char smc[];
    __nv_bfloat16* sb = (__nv_bfloat16*)smc;
    const uint32_t smb = smem_u32(smc);

    const int tid = threadIdx.x, wid = tid >> 5, lane = tid & 31;
    const int wq = wid * 16;
    const int qt = blockIdx.x, h = blockIdx.y, b = blockIdx.z;
    const float scale = scale_p[0];
    const int tr  = lane >> 2;
    const int tc2 = 2 * (lane & 3);

    // ---- load Q tiles (hi+lo) ----
    {
        const int r = tid >> 1, c = (tid & 1) * 32;
        const size_t go = ((size_t)(b * Tlen + qt * 128 + r)) * EMB + h * HD + c;
        const uint4* s0 = (const uint4*)(qh + go);
        const uint4* s1 = (const uint4*)(ql + go);
        uint4* d0 = (uint4*)(sb + QH0 + r * LDT + c);
        uint4* d1 = (uint4*)(sb + QL0 + r * LDT + c);
#pragma unroll
        for (int j = 0; j < 4; j++) { d0[j] = s0[j]; d1[j] = s1[j]; }
    }
    __syncthreads();

    // ---- Q A-frags, hoisted for the whole kernel ----
    uint32_t fqh[4][4], fql[4][4];
    {
        const uint32_t arow = wq + (lane & 15);
        const uint32_t akk  = (lane >> 4) * 8;
#pragma unroll
        for (int ks = 0; ks < 4; ks++) {
            ldsm_x4(fqh[ks][0], fqh[ks][1], fqh[ks][2], fqh[ks][3],
                    smb + (QH0 + arow * LDT + ks * 16 + akk) * 2);
            ldsm_x4(fql[ks][0], fql[ks][1], fql[ks][2], fql[ks][3],
                    smb + (QL0 + arow * LDT + ks * 16 + akk) * 2);
        }
    }

    float m0 = -INFINITY, m1 = -INFINITY, l0 = 0.f, l1 = 0.f;
    float o[8][4];
#pragma unroll
    for (int nd = 0; nd < 8; nd++)
#pragma unroll
        for (int e = 0; e < 4; e++) o[nd][e] = 0.f;

    const int ktd  = qt * 2 + (wid >> 2);       // diagonal key tile for this warp
    const int rel0 = (wid & 3) * 16 + tr;       // row position within 64-chunk

    for (int kt = 0; kt < 16; kt++) {
        __syncthreads();
        {   // load K/V tiles (hi+lo), 64x64 each
            const int r = tid >> 2, c = (tid & 3) * 16;
            const size_t go = ((size_t)(b * Tlen + kt * 64 + r)) * EMB + h * HD + c;
            uint4* dk0 = (uint4*)(sb + KH0 + r * LDT + c);
            uint4* dk1 = (uint4*)(sb + KL0 + r * LDT + c);
            uint4* dv0 = (uint4*)(sb + VH0 + r * LDT + c);
            uint4* dv1 = (uint4*)(sb + VL0 + r * LDT + c);
            const uint4* sk0 = (const uint4*)(kh + go);
            const uint4* sk1 = (const uint4*)(kl + go);
            const uint4* sv0 = (const uint4*)(vh + go);
            const uint4* sv1 = (const uint4*)(vl + go);
#pragma unroll
            for (int j = 0; j < 2; j++) {
                dk0[j] = sk0[j]; dk1[j] = sk1[j];
                dv0[j] = sv0[j]; dv1[j] = sv1[j];
            }
        }
        __syncthreads();

        // ---- S = Q.K^T (3-term split), 8 n-tiles of 8 keys ----
        float s[8][4];
#pragma unroll
        for (int ni = 0; ni < 8; ni++)
#pragma unroll
            for (int e = 0; e < 4; e++) s[ni][e] = 0.f;

#pragma unroll
        for (int ni = 0; ni < 8; ni += 2) {
#pragma unroll
            for (int ks = 0; ks < 4; ks++) {
                uint32_t kh4[4], kl4[4];
                const uint32_t boff =
                    ((ni + (lane >> 4)) * 8 + (lane & 7)) * LDT
                    + ks * 16 + ((lane >> 3) & 1) * 8;
                ldsm_x4(kh4[0], kh4[1], kh4[2], kh4[3], smb + (KH0 + boff) * 2);
                ldsm_x4(kl4[0], kl4[1], kl4[2], kl4[3], smb + (KL0 + boff) * 2);
                mma16816(s[ni],     fqh[ks], kh4);
                mma16816(s[ni],     fqh[ks], kl4);
                mma16816(s[ni],     fql[ks], kh4);
                mma16816(s[ni + 1], fqh[ks], kh4 + 2);
                mma16816(s[ni + 1], fqh[ks], kl4 + 2);
                mma16816(s[ni + 1], fql[ks], kh4 + 2);
            }
        }

        // scale + mask (diagonal chunk tile only)
#pragma unroll
        for (int ni = 0; ni < 8; ni++)
#pragma unroll
            for (int e = 0; e < 4; e++) s[ni][e] *= scale;
        if (kt == ktd) {
#pragma unroll
            for (int ni = 0; ni < 8; ni++) {
                const int c0 = ni * 8 + tc2;
                if (c0     > rel0)     s[ni][0] = -INFINITY;
                if (c0 + 1 > rel0)     s[ni][1] = -INFINITY;
                if (c0     > rel0 + 8) s[ni][2] = -INFINITY;
                if (c0 + 1 > rel0 + 8) s[ni][3] = -INFINITY;
            }
        }

        // ---- online softmax (rows tr and tr+8) ----
        float tm0 = -INFINITY, tm1 = -INFINITY;
#pragma unroll
        for (int ni = 0; ni < 8; ni++) {
            tm0 = fmaxf(tm0, fmaxf(s[ni][0], s[ni][1]));
            tm1 = fmaxf(tm1, fmaxf(s[ni][2], s[ni][3]));
        }
        tm0 = fmaxf(tm0, __shfl_xor_sync(0xffffffffu, tm0, 1));
        tm0 = fmaxf(tm0, __shfl_xor_sync(0xffffffffu, tm0, 2));
        tm1 = fmaxf(tm1, __shfl_xor_sync(0xffffffffu, tm1, 1));
        tm1 = fmaxf(tm1, __shfl_xor_sync(0xffffffffu, tm1, 2));
        const float mn0 = fmaxf(m0, tm0), mn1 = fmaxf(m1, tm1);
        const float co0 = __expf(m0 - mn0), co1 = __expf(m1 - mn1);

        float ts0 = 0.f, ts1 = 0.f;
#pragma unroll
        for (int ni = 0; ni < 8; ni++) {
            s[ni][0] = __expf(s[ni][0] - mn0); ts0 += s[ni][0];
            s[ni][1] = __expf(s[ni][1] - mn0); ts0 += s[ni][1];
            s[ni][2] = __expf(s[ni][2] - mn1); ts1 += s[ni][2];
            s[ni][3] = __expf(s[ni][3] - mn1); ts1 += s[ni][3];
        }
        ts0 += __shfl_xor_sync(0xffffffffu, ts0, 1);
        ts0 += __shfl_xor_sync(0xffffffffu, ts0, 2);
        ts1 += __shfl_xor_sync(0xffffffffu, ts1, 1);
        ts1 += __shfl_xor_sync(0xffffffffu, ts1, 2);
        l0 = l0 * co0 + ts0; l1 = l1 * co1 + ts1;
        m0 = mn0; m1 = mn1;
#pragma unroll
        for (int nd = 0; nd < 8; nd++) {
            o[nd][0] *= co0; o[nd][1] *= co0;
            o[nd][2] *= co1; o[nd][3] *= co1;
        }

        // ---- O += P.V (register-only P repack; V via ldmatrix.trans) ----
#pragma unroll
        for (int kp = 0; kp < 4; kp++) {
            uint32_t fph[4], fpl[4];
            pack_pair(s[2 * kp][0],     s[2 * kp][1],     fph[0], fpl[0]);
            pack_pair(s[2 * kp][2],     s[2 * kp][3],     fph[1], fpl[1]);
            pack_pair(s[2 * kp + 1][0], s[2 * kp + 1][1], fph[2], fpl[2]);
            pack_pair(s[2 * kp + 1][2], s[2 * kp + 1][3], fph[3], fpl[3]);
#pragma unroll
            for (int nd = 0; nd < 8; nd += 2) {
                uint32_t fvh[4], fvl[4];
                const uint32_t voff =
                    (kp * 16 + (lane & 15)) * LDT + (nd + (lane >> 4)) * 8;
                ldsm_x4_t(fvh, smb + (VH0 + voff) * 2);
                ldsm_x4_t(fvl, smb + (VL0 + voff) * 2);
                mma16816(o[nd],     fph, fvh);
                mma16816(o[nd],     fph, fvl);
                mma16816(o[nd],     fpl, fvh);
                mma16816(o[nd + 1], fph, fvh + 2);
                mma16816(o[nd + 1], fph, fvl + 2);
                mma16816(o[nd + 1], fpl, fvh + 2);
            }
        }
    }

    // ---- finalize: normalize, split to bf16 hi/lo, store ----
    const float i0 = 1.f / l0, i1 = 1.f / l1;
    const size_t row0 = (size_t)(b * Tlen + qt * 128 + wq + tr);
#pragma unroll
    for (int nd = 0; nd < 8; nd++) {
        const int col = h * HD + nd * 8 + tc2;
        split_store(oh, ol, row0 * EMB + col,
                    o[nd][0] * i0, o[nd][1] * i0);
        split_store(oh, ol, (row0 + 8) * EMB + col,
                    o[nd][2] * i1, o[nd][3] * i1);
    }
}

// ---------------------------------------------------------------------------
// Launch
// ---------------------------------------------------------------------------
extern "C" void kernel_launch(void* const* d_in, const int* in_sizes, int n_in,
                              void* d_out, int out_size)
{
    const float* x     = (const float*)d_in[0];
    const float* Wq    = (const float*)d_in[1];
    const float* bq    = (const float*)d_in[2];
    const float* Wk    = (const float*)d_in[3];
    const float* bk    = (const float*)d_in[4];
    const float* Wv    = (const float*)d_in[5];
    const float* bv    = (const float*)d_in[6];
    const float* Wo    = (const float*)d_in[7];
    const float* bo    = (const float*)d_in[8];
    const float* ascl  = (const float*)d_in[9];
    float* out = (float*)d_out;

    __nv_bfloat16 *xh, *xl, *qh, *ql, *kh, *kl, *vh, *vl, *ah, *al;
    __nv_bfloat16 *wqh, *wql, *wkh, *wkl, *wvh, *wvl, *woh, *wol;
    cudaGetSymbolAddress((void**)&xh, g_xh);   cudaGetSymbolAddress((void**)&xl, g_xl);
    cudaGetSymbolAddress((void**)&qh, g_qh);   cudaGetSymbolAddress((void**)&ql, g_ql);
    cudaGetSymbolAddress((void**)&kh, g_kh);   cudaGetSymbolAddress((void**)&kl, g_kl);
    cudaGetSymbolAddress((void**)&vh, g_vh);   cudaGetSymbolAddress((void**)&vl, g_vl);
    cudaGetSymbolAddress((void**)&ah, g_ah);   cudaGetSymbolAddress((void**)&al, g_al);
    cudaGetSymbolAddress((void**)&wqh, g_wqh); cudaGetSymbolAddress((void**)&wql, g_wql);
    cudaGetSymbolAddress((void**)&wkh, g_wkh); cudaGetSymbolAddress((void**)&wkl, g_wkl);
    cudaGetSymbolAddress((void**)&wvh, g_wvh); cudaGetSymbolAddress((void**)&wvl, g_wvl);
    cudaGetSymbolAddress((void**)&woh, g_woh); cudaGetSymbolAddress((void**)&wol, g_wol);

    const int nX = MTOT * EMB;     // 8M
    const int nW = EMB * EMB;      // 1M
    cvt_split<<<nX / 1024, 256>>>(x,  xh,  xl,  nX);
    cvt_split<<<nW / 1024, 256>>>(Wq, wqh, wql, nW);
    cvt_split<<<nW / 1024, 256>>>(Wk, wkh, wkl, nW);
    cvt_split<<<nW / 1024, 256>>>(Wv, wvh, wvl, nW);
    cvt_split<<<nW / 1024, 256>>>(Wo, woh, wol, nW);

    cudaFuncSetAttribute(gemm_qkv_tc, cudaFuncAttributeMaxDynamicSharedMemorySize, SMEM_MMA);
    cudaFuncSetAttribute(gemm_o_tc,   cudaFuncAttributeMaxDynamicSharedMemorySize, SMEM_MMA);
    cudaFuncSetAttribute(attn_mma,    cudaFuncAttributeMaxDynamicSharedMemorySize, ATT_SMEM);

    // QKV projections (tensor cores, split bf16 outputs): grid (24, 64)
    dim3 qkvGrid(24, MTOT / 128);
    gemm_qkv_tc<<<qkvGrid, 256, SMEM_MMA>>>(xh, xl, wqh, wql, wkh, wkl, wvh, wvl,
                                            bq, bk, bv, qh, ql, kh, kl, vh, vl);

    // Tensor-core attention: grid (8, 16, 8), writes ah/al split
    dim3 agrid(Tlen / 128, NHEADS, Bsz);
    attn_mma<<<agrid, 256, ATT_SMEM>>>(qh, ql, kh, kl, vh, vl, ascl, ah, al);

    // Output projection (fp32 out)
    dim3 ogrid(EMB / 128, MTOT / 128);
    gemm_o_tc<<<ogrid, 256, SMEM_MMA>>>(ah, al, woh, wol, bo, out);
}

// round 14
// speedup vs baseline: 3.1901x; 1.4512x over previous
#include <cuda_runtime.h>
#include <cuda_fp16.h>
#include <math.h>
#include <stdint.h>

// Problem constants
#define Bsz    8
#define Tlen   1024
#define EMB    1024
#define NHEADS 16
#define HD     64

#define MTOT (Bsz * Tlen)          // 8192 rows

// ---------------------------------------------------------------------------
// Scratch (device globals — allocation-free per harness rules).
// fp16 scheme: activations split hi/lo (exact), weights/K/V single fp16.
// ---------------------------------------------------------------------------
__device__ __half g_xh[MTOT * EMB], g_xl[MTOT * EMB];
__device__ __half g_qh[MTOT * EMB], g_ql[MTOT * EMB];
__device__ __half g_k1[MTOT * EMB];
__device__ __half g_v1[MTOT * EMB];
__device__ __half g_ah[MTOT * EMB], g_al[MTOT * EMB];
__device__ __half g_wq1[EMB * EMB], g_wk1[EMB * EMB];
__device__ __half g_wv1[EMB * EMB], g_wo1[EMB * EMB];

// ---------------------------------------------------------------------------
// Warp MMA helpers (mma.sync + ldmatrix — plain sm_103 features only)
// ---------------------------------------------------------------------------
__device__ __forceinline__ uint32_t smem_u32(const void* p) {
    uint32_t a;
    asm("{ .reg .u64 t; cvta.to.shared.u64 t, %1; cvt.u32.u64 %0, t; }"
        : "=r"(a) : "l"(p));
    return a;
}

__device__ __forceinline__ void ldsm_x4(uint32_t& r0, uint32_t& r1,
                                        uint32_t& r2, uint32_t& r3, uint32_t a) {
    asm volatile("ldmatrix.sync.aligned.m8n8.x4.shared.b16 {%0,%1,%2,%3}, [%4];"
                 : "=r"(r0), "=r"(r1), "=r"(r2), "=r"(r3) : "r"(a));
}
__device__ __forceinline__ void ldsm_x4_t(uint32_t* r, uint32_t a) {
    asm volatile("ldmatrix.sync.aligned.m8n8.x4.trans.shared.b16 {%0,%1,%2,%3}, [%4];"
                 : "=r"(r[0]), "=r"(r[1]), "=r"(r[2]), "=r"(r[3]) : "r"(a));
}
__device__ __forceinline__ void ldsm_x2(uint32_t& r0, uint32_t& r1, uint32_t a) {
    asm volatile("ldmatrix.sync.aligned.m8n8.x2.shared.b16 {%0,%1}, [%2];"
                 : "=r"(r0), "=r"(r1) : "r"(a));
}

__device__ __forceinline__ void mma16816(float* c, const uint32_t* a,
                                         const uint32_t* b) {
    asm volatile(
        "mma.sync.aligned.m16n8k16.row.col.f32.f16.f16.f32 "
        "{%0,%1,%2,%3}, {%4,%5,%6,%7}, {%8,%9}, {%0,%1,%2,%3};"
        : "+f"(c[0]), "+f"(c[1]), "+f"(c[2]), "+f"(c[3])
        : "r"(a[0]), "r"(a[1]), "r"(a[2]), "r"(a[3]), "r"(b[0]), "r"(b[1]));
}

// split a,b (fp32) into packed fp16 hi/lo pair registers
__device__ __forceinline__ void pack_pair(float a, float b,
                                          uint32_t& hreg, uint32_t& lreg) {
    __half ha = __float2half(a);
    __half hb = __float2half(b);
    __half2 hp; hp.x = ha; hp.y = hb;
    hreg = *(uint32_t*)&hp;
    __half2 lp;
    lp.x = __float2half(a - __half2float(ha));
    lp.y = __float2half(b - __half2float(hb));
    lreg = *(uint32_t*)&lp;
}

__device__ __forceinline__ void split_store(__half* h, __half* l,
                                            size_t idx, float a, float b) {
    __half ha = __float2half(a);
    __half hb = __float2half(b);
    __half2 hp; hp.x = ha; hp.y = hb;
    *(__half2*)(h + idx) = hp;
    __half2 lp;
    lp.x = __float2half(a - __half2float(ha));
    lp.y = __float2half(b - __half2float(hb));
    *(__half2*)(l + idx) = lp;
}

// ---------------------------------------------------------------------------
// fp32 -> fp16 conversions
// ---------------------------------------------------------------------------
__global__ __launch_bounds__(256)
void cvt_split(const float* __restrict__ s, __half* __restrict__ h,
               __half* __restrict__ l, int n)
{
    int i = (blockIdx.x * 256 + threadIdx.x) * 4;
    if (i >= n) return;
    float4 v = *(const float4*)(s + i);
    float vv[4] = {v.x, v.y, v.z, v.w};
#pragma unroll
    for (int t = 0; t < 4; t += 2) {
        split_store(h, l, i + t, vv[t], vv[t + 1]);
    }
}

__global__ __launch_bounds__(256)
void cvt_h(const float* __restrict__ s, __half* __restrict__ h, int n)
{
    int i = (blockIdx.x * 256 + threadIdx.x) * 4;
    if (i >= n) return;
    float4 v = *(const float4*)(s + i);
    __half2 p0; p0.x = __float2half(v.x); p0.y = __float2half(v.y);
    __half2 p1; p1.x = __float2half(v.z); p1.y = __float2half(v.w);
    *(__half2*)(h + i)     = p0;
    *(__half2*)(h + i + 2) = p1;
}

// ---------------------------------------------------------------------------
// fp16 2-term tensor GEMM: C tile 128x128 of A[M,1024]*B[N,1024]^T + bias.
// C = Ah*Bh + Al*Bh = A*Bh (A-split exact), fp32 accum.
// Smem: 3 tiles (Ah, Al, Bh) of 128x(32+8) fp16, double-buffered.
// Epilogue modes (runtime, uniform): fp32 C, split (Ch+Cl), or single Ch.
// ---------------------------------------------------------------------------
#define TCK   32
#define NCHK  (EMB / TCK)
#define TLD   40
#define TILE_B (128 * TLD * 2)
#define BUF_B  (3 * TILE_B)
#define SMEM_MMA (2 * BUF_B)        // 61440 B

__device__ __forceinline__
void ld_chunk(uint4* v,
              const __half* Ah0, const __half* Al0, const __half* Bh0,
              int row, int col, int kc)
{
    const size_t off = (size_t)row * EMB + kc + col;
    v[0] = *(const uint4*)(Ah0 + off); v[1] = *(const uint4*)(Ah0 + off + 8);
    v[2] = *(const uint4*)(Al0 + off); v[3] = *(const uint4*)(Al0 + off + 8);
    v[4] = *(const uint4*)(Bh0 + off); v[5] = *(const uint4*)(Bh0 + off + 8);
}

__device__ __forceinline__
void st_chunk(char* smbuf, const uint4* v, int row, int col)
{
    const uint32_t off = (uint32_t)(row * TLD + col) * 2;
    *(uint4*)(smbuf + 0 * TILE_B + off)      = v[0];
    *(uint4*)(smbuf + 0 * TILE_B + off + 16) = v[1];
    *(uint4*)(smbuf + 1 * TILE_B + off)      = v[2];
    *(uint4*)(smbuf + 1 * TILE_B + off + 16) = v[3];
    *(uint4*)(smbuf + 2 * TILE_B + off)      = v[4];
    *(uint4*)(smbuf + 2 * TILE_B + off + 16) = v[5];
}

__device__ __forceinline__
void gemm_mma_body(const __half* __restrict__ ah, const __half* __restrict__ al,
                   const __half* __restrict__ bh,
                   const float* __restrict__ bias,
                   float* __restrict__ C,
                   __half* __restrict__ Ch, __half* __restrict__ Cl,
                   int mBase, int nBase)
{
    extern __shared__ char sm[];
    const uint32_t smb = smem_u32(sm);

    const int tid  = threadIdx.x;
    const int wid  = tid >> 5;
    const int lane = tid & 31;
    const int wm = (wid >> 2) * 64;
    const int wn = (wid & 3) * 32;

    const int grow = tid >> 1;
    const int gcol = (tid & 1) * 16;

    const __half* Ah0 = ah + (size_t)mBase * EMB;
    const __half* Al0 = al + (size_t)mBase * EMB;
    const __half* Bh0 = bh + (size_t)nBase * EMB;

    const uint32_t aRow = wm + (lane & 15);
    const uint32_t aK   = (lane >> 4) * 8;
    const uint32_t bRow = wn + (lane & 7);
    const uint32_t bK   = ((lane >> 3) & 1) * 8;

    float acc[4][4][4];
#pragma unroll
    for (int mi = 0; mi < 4; mi++)
#pragma unroll
        for (int ni = 0; ni < 4; ni++)
#pragma unroll
            for (int e = 0; e < 4; e++) acc[mi][ni][e] = 0.f;

    {
        uint4 v[6];
        ld_chunk(v, Ah0, Al0, Bh0, grow, gcol, 0);
        st_chunk(sm, v, grow, gcol);
    }
    __syncthreads();

    int buf = 0;
    for (int c = 0; c < NCHK; c++) {
        const bool more = (c + 1) < NCHK;
        uint4 pf[6];
        if (more) ld_chunk(pf, Ah0, Al0, Bh0, grow, gcol, (c + 1) * TCK);

        const uint32_t bb = smb + buf * BUF_B;
#pragma unroll
        for (int k16 = 0; k16 < 2; k16++) {
            const uint32_t kb = k16 * 16;
            uint32_t fah[4][4], fal[4][4], fbh[4][2];
#pragma unroll
            for (int mi = 0; mi < 4; mi++) {
                uint32_t ao = ((aRow + mi * 16) * TLD + kb + aK) * 2;
                ldsm_x4(fah[mi][0], fah[mi][1], fah[mi][2], fah[mi][3],
                        bb + 0 * TILE_B + ao);
                ldsm_x4(fal[mi][0], fal[mi][1], fal[mi][2], fal[mi][3],
                        bb + 1 * TILE_B + ao);
            }
#pragma unroll
            for (int ni = 0; ni < 4; ni++) {
                uint32_t bo = ((bRow + ni * 8) * TLD + kb + bK) * 2;
                ldsm_x2(fbh[ni][0], fbh[ni][1], bb + 2 * TILE_B + bo);
            }
#pragma unroll
            for (int mi = 0; mi < 4; mi++)
#pragma unroll
                for (int ni = 0; ni < 4; ni++) {
                    mma16816(acc[mi][ni], fah[mi], fbh[ni]);
                    mma16816(acc[mi][ni], fal[mi], fbh[ni]);
                }
        }

        if (more) {
            const int nb = buf ^ 1;
            st_chunk(sm + nb * BUF_B, pf, grow, gcol);
            __syncthreads();
            buf = nb;
        }
    }

    const int tr = lane >> 2;
    const int tc = (lane & 3) * 2;
#pragma unroll
    for (int mi = 0; mi < 4; mi++) {
        const int gm0 = mBase + wm + mi * 16 + tr;
#pragma unroll
        for (int ni = 0; ni < 4; ni++) {
            const int gn = nBase + wn + ni * 8 + tc;
            const float b0 = bias[gn], b1 = bias[gn + 1];
            float v0 = acc[mi][ni][0] + b0, v1 = acc[mi][ni][1] + b1;
            float v2 = acc[mi][ni][2] + b0, v3 = acc[mi][ni][3] + b1;
            if (C) {
                *(float2*)(C + (size_t)gm0 * EMB + gn)       = make_float2(v0, v1);
                *(float2*)(C + (size_t)(gm0 + 8) * EMB + gn) = make_float2(v2, v3);
            } else if (Cl) {
                split_store(Ch, Cl, (size_t)gm0 * EMB + gn, v0, v1);
                split_store(Ch, Cl, (size_t)(gm0 + 8) * EMB + gn, v2, v3);
            } else {
                __half2 p0; p0.x = __float2half(v0); p0.y = __float2half(v1);
                __half2 p1; p1.x = __float2half(v2); p1.y = __float2half(v3);
                *(__half2*)(Ch + (size_t)gm0 * EMB + gn)       = p0;
                *(__half2*)(Ch + (size_t)(gm0 + 8) * EMB + gn) = p1;
            }
        }
    }
}

// Fused QKV: grid (24, 64). Q -> split hi/lo; K, V -> single fp16.
__global__ __launch_bounds__(256)
void gemm_qkv_tc(const __half* __restrict__ xh, const __half* __restrict__ xl,
                 const __half* __restrict__ wq1, const __half* __restrict__ wk1,
                 const __half* __restrict__ wv1,
                 const float* __restrict__ bq, const float* __restrict__ bk,
                 const float* __restrict__ bv,
                 __half* __restrict__ qh, __half* __restrict__ ql,
                 __half* __restrict__ k1, __half* __restrict__ v1)
{
    const int sel = blockIdx.x >> 3;
    const int nb  = blockIdx.x & 7;
    const __half* wh  = (sel == 0) ? wq1 : (sel == 1) ? wk1 : wv1;
    const float* bias = (sel == 0) ? bq  : (sel == 1) ? bk  : bv;
    __half* Ch        = (sel == 0) ? qh  : (sel == 1) ? k1  : v1;
    __half* Cl        = (sel == 0) ? ql  : nullptr;
    gemm_mma_body(xh, xl, wh, bias, nullptr, Ch, Cl,
                  blockIdx.y * 128, nb * 128);
}

// Output projection (fp32 output): grid (8, 64)
__global__ __launch_bounds__(256)
void gemm_o_tc(const __half* __restrict__ ah, const __half* __restrict__ al,
               const __half* __restrict__ wo1,
               const float* __restrict__ bias, float* __restrict__ C)
{
    gemm_mma_body(ah, al, wo1, bias, C, nullptr, nullptr,
                  blockIdx.y * 128, blockIdx.x * 128);
}

// ---------------------------------------------------------------------------
// Tensor-core flash attention, fp16 2-term split (Q and P split; K, V single).
// CTA = (q-tile 128, head, batch); 8 warps x 16 q-rows. Key tiles of 64.
// S = (Qh+Ql).K^T exact in Q; PV = (Ph+Pl).V exact in P; fp32 softmax.
// Mask: only the diagonal 64-chunk tile, upper-triangular.
// Output written directly as fp16 hi/lo split for the O-projection.
// ---------------------------------------------------------------------------
#define LDT 72
#define QH0 0
#define QL0 (128 * LDT)
#define KH0 (2 * 128 * LDT)
#define VH0 (KH0 + 64 * LDT)
#define ATT_SMEM ((2 * 128 * LDT + 2 * 64 * LDT) * 2)   // 55,296 B

__global__ __launch_bounds__(256)
void attn_mma(const __half* __restrict__ qh, const __half* __restrict__ ql,
              const __half* __restrict__ k1, const __half* __restrict__ v1,
              const float* __restrict__ scale_p,
              __half* __restrict__ oh, __half* __restrict__ ol)
{
    extern __shared__ char smc[];
    __half* sb = (__half*)smc;
    const uint32_t smb = smem_u32(smc);

    const int tid = threadIdx.x, wid = tid >> 5, lane = tid & 31;
    const int wq = wid * 16;
    const int qt = blockIdx.x, h = blockIdx.y, b = blockIdx.z;
    const float scale = scale_p[0];
    const int tr  = lane >> 2;
    const int tc2 = 2 * (lane & 3);

    // ---- load Q tiles (hi+lo) ----
    {
        const int r = tid >> 1, c = (tid & 1) * 32;
        const size_t go = ((size_t)(b * Tlen + qt * 128 + r)) * EMB + h * HD + c;
        const uint4* s0 = (const uint4*)(qh + go);
        const uint4* s1 = (const uint4*)(ql + go);
        uint4* d0 = (uint4*)(sb + QH0 + r * LDT + c);
        uint4* d1 = (uint4*)(sb + QL0 + r * LDT + c);
#pragma unroll
        for (int j = 0; j < 4; j++) { d0[j] = s0[j]; d1[j] = s1[j]; }
    }
    __syncthreads();

    // ---- Q A-frags, hoisted ----
    uint32_t fqh[4][4], fql[4][4];
    {
        const uint32_t arow = wq + (lane & 15);
        const uint32_t akk  = (lane >> 4) * 8;
#pragma unroll
        for (int ks = 0; ks < 4; ks++) {
            ldsm_x4(fqh[ks][0], fqh[ks][1], fqh[ks][2], fqh[ks][3],
                    smb + (QH0 + arow * LDT + ks * 16 + akk) * 2);
            ldsm_x4(fql[ks][0], fql[ks][1], fql[ks][2], fql[ks][3],
                    smb + (QL0 + arow * LDT + ks * 16 + akk) * 2);
        }
    }

    float m0 = -INFINITY, m1 = -INFINITY, l0 = 0.f, l1 = 0.f;
    float o[8][4];
#pragma unroll
    for (int nd = 0; nd < 8; nd++)
#pragma unroll
        for (int e = 0; e < 4; e++) o[nd][e] = 0.f;

    const int ktd  = qt * 2 + (wid >> 2);
    const int rel0 = (wid & 3) * 16 + tr;

    for (int kt = 0; kt < 16; kt++) {
        __syncthreads();
        {   // load K/V tiles (single fp16), 64x64 each
            const int r = tid >> 2, c = (tid & 3) * 16;
            const size_t go = ((size_t)(b * Tlen + kt * 64 + r)) * EMB + h * HD + c;
            uint4* dk = (uint4*)(sb + KH0 + r * LDT + c);
            uint4* dv = (uint4*)(sb + VH0 + r * LDT + c);
            const uint4* skp = (const uint4*)(k1 + go);
            const uint4* svp = (const uint4*)(v1 + go);
#pragma unroll
            for (int j = 0; j < 2; j++) { dk[j] = skp[j]; dv[j] = svp[j]; }
        }
        __syncthreads();

        // ---- S = Q.K^T (Q-split, K single) ----
        float s[8][4];
#pragma unroll
        for (int ni = 0; ni < 8; ni++)
#pragma unroll
            for (int e = 0; e < 4; e++) s[ni][e] = 0.f;

#pragma unroll
        for (int ni = 0; ni < 8; ni += 2) {
#pragma unroll
            for (int ks = 0; ks < 4; ks++) {
                uint32_t kh4[4];
                const uint32_t boff =
                    ((ni + (lane >> 4)) * 8 + (lane & 7)) * LDT
                    + ks * 16 + ((lane >> 3) & 1) * 8;
                ldsm_x4(kh4[0], kh4[1], kh4[2], kh4[3], smb + (KH0 + boff) * 2);
                mma16816(s[ni],     fqh[ks], kh4);
                mma16816(s[ni],     fql[ks], kh4);
                mma16816(s[ni + 1], fqh[ks], kh4 + 2);
                mma16816(s[ni + 1], fql[ks], kh4 + 2);
            }
        }

        // scale + mask (diagonal chunk tile only)
#pragma unroll
        for (int ni = 0; ni < 8; ni++)
#pragma unroll
            for (int e = 0; e < 4; e++) s[ni][e] *= scale;
        if (kt == ktd) {
#pragma unroll
            for (int ni = 0; ni < 8; ni++) {
                const int c0 = ni * 8 + tc2;
                if (c0     > rel0)     s[ni][0] = -INFINITY;
                if (c0 + 1 > rel0)     s[ni][1] = -INFINITY;
                if (c0     > rel0 + 8) s[ni][2] = -INFINITY;
                if (c0 + 1 > rel0 + 8) s[ni][3] = -INFINITY;
            }
        }

        // ---- online softmax (rows tr and tr+8) ----
        float tm0 = -INFINITY, tm1 = -INFINITY;
#pragma unroll
        for (int ni = 0; ni < 8; ni++) {
            tm0 = fmaxf(tm0, fmaxf(s[ni][0], s[ni][1]));
            tm1 = fmaxf(tm1, fmaxf(s[ni][2], s[ni][3]));
        }
        tm0 = fmaxf(tm0, __shfl_xor_sync(0xffffffffu, tm0, 1));
        tm0 = fmaxf(tm0, __shfl_xor_sync(0xffffffffu, tm0, 2));
        tm1 = fmaxf(tm1, __shfl_xor_sync(0xffffffffu, tm1, 1));
        tm1 = fmaxf(tm1, __shfl_xor_sync(0xffffffffu, tm1, 2));
        const float mn0 = fmaxf(m0, tm0), mn1 = fmaxf(m1, tm1);
        const float co0 = __expf(m0 - mn0), co1 = __expf(m1 - mn1);

        float ts0 = 0.f, ts1 = 0.f;
#pragma unroll
        for (int ni = 0; ni < 8; ni++) {
            s[ni][0] = __expf(s[ni][0] - mn0); ts0 += s[ni][0];
            s[ni][1] = __expf(s[ni][1] - mn0); ts0 += s[ni][1];
            s[ni][2] = __expf(s[ni][2] - mn1); ts1 += s[ni][2];
            s[ni][3] = __expf(s[ni][3] - mn1); ts1 += s[ni][3];
        }
        ts0 += __shfl_xor_sync(0xffffffffu, ts0, 1);
        ts0 += __shfl_xor_sync(0xffffffffu, ts0, 2);
        ts1 += __shfl_xor_sync(0xffffffffu, ts1, 1);
        ts1 += __shfl_xor_sync(0xffffffffu, ts1, 2);
        l0 = l0 * co0 + ts0; l1 = l1 * co1 + ts1;
        m0 = mn0; m1 = mn1;
#pragma unroll
        for (int nd = 0; nd < 8; nd++) {
            o[nd][0] *= co0; o[nd][1] *= co0;
            o[nd][2] *= co1; o[nd][3] *= co1;
        }

        // ---- O += P.V (P split in-register; V single via ldmatrix.trans) ----
#pragma unroll
        for (int kp = 0; kp < 4; kp++) {
            uint32_t fph[4], fpl[4];
            pack_pair(s[2 * kp][0],     s[2 * kp][1],     fph[0], fpl[0]);
            pack_pair(s[2 * kp][2],     s[2 * kp][3],     fph[1], fpl[1]);
            pack_pair(s[2 * kp + 1][0], s[2 * kp + 1][1], fph[2], fpl[2]);
            pack_pair(s[2 * kp + 1][2], s[2 * kp + 1][3], fph[3], fpl[3]);
#pragma unroll
            for (int nd = 0; nd < 8; nd += 2) {
                uint32_t fvh[4];
                const uint32_t voff =
                    (kp * 16 + (lane & 15)) * LDT + (nd + (lane >> 4)) * 8;
                ldsm_x4_t(fvh, smb + (VH0 + voff) * 2);
                mma16816(o[nd],     fph, fvh);
                mma16816(o[nd],     fpl, fvh);
                mma16816(o[nd + 1], fph, fvh + 2);
                mma16816(o[nd + 1], fpl, fvh + 2);
            }
        }
    }

    // ---- finalize: normalize, split to fp16 hi/lo, store ----
    const float i0 = 1.f / l0, i1 = 1.f / l1;
    const size_t row0 = (size_t)(b * Tlen + qt * 128 + wq + tr);
#pragma unroll
    for (int nd = 0; nd < 8; nd++) {
        const int col = h * HD + nd * 8 + tc2;
        split_store(oh, ol, row0 * EMB + col,
                    o[nd][0] * i0, o[nd][1] * i0);
        split_store(oh, ol, (row0 + 8) * EMB + col,
                    o[nd][2] * i1, o[nd][3] * i1);
    }
}

// ---------------------------------------------------------------------------
// Launch
// ---------------------------------------------------------------------------
extern "C" void kernel_launch(void* const* d_in, const int* in_sizes, int n_in,
                              void* d_out, int out_size)
{
    const float* x     = (const float*)d_in[0];
    const float* Wq    = (const float*)d_in[1];
    const float* bq    = (const float*)d_in[2];
    const float* Wk    = (const float*)d_in[3];
    const float* bk    = (const float*)d_in[4];
    const float* Wv    = (const float*)d_in[5];
    const float* bv    = (const float*)d_in[6];
    const float* Wo    = (const float*)d_in[7];
    const float* bo    = (const float*)d_in[8];
    const float* ascl  = (const float*)d_in[9];
    float* out = (float*)d_out;

    __half *xh, *xl, *qh, *ql, *k1, *v1, *ah, *al;
    __half *wq1, *wk1, *wv1, *wo1;
    cudaGetSymbolAddress((void**)&xh, g_xh);   cudaGetSymbolAddress((void**)&xl, g_xl);
    cudaGetSymbolAddress((void**)&qh, g_qh);   cudaGetSymbolAddress((void**)&ql, g_ql);
    cudaGetSymbolAddress((void**)&k1, g_k1);   cudaGetSymbolAddress((void**)&v1, g_v1);
    cudaGetSymbolAddress((void**)&ah, g_ah);   cudaGetSymbolAddress((void**)&al, g_al);
    cudaGetSymbolAddress((void**)&wq1, g_wq1); cudaGetSymbolAddress((void**)&wk1, g_wk1);
    cudaGetSymbolAddress((void**)&wv1, g_wv1); cudaGetSymbolAddress((void**)&wo1, g_wo1);

    const int nX = MTOT * EMB;     // 8M
    const int nW = EMB * EMB;      // 1M
    cvt_split<<<nX / 1024, 256>>>(x, xh, xl, nX);
    cvt_h<<<nW / 1024, 256>>>(Wq, wq1, nW);
    cvt_h<<<nW / 1024, 256>>>(Wk, wk1, nW);
    cvt_h<<<nW / 1024, 256>>>(Wv, wv1, nW);
    cvt_h<<<nW / 1024, 256>>>(Wo, wo1, nW);

    cudaFuncSetAttribute(gemm_qkv_tc, cudaFuncAttributeMaxDynamicSharedMemorySize, SMEM_MMA);
    cudaFuncSetAttribute(gemm_o_tc,   cudaFuncAttributeMaxDynamicSharedMemorySize, SMEM_MMA);
    cudaFuncSetAttribute(attn_mma,    cudaFuncAttributeMaxDynamicSharedMemorySize, ATT_SMEM);

    // QKV projections: grid (24, 64)
    dim3 qkvGrid(24, MTOT / 128);
    gemm_qkv_tc<<<qkvGrid, 256, SMEM_MMA>>>(xh, xl, wq1, wk1, wv1,
                                            bq, bk, bv, qh, ql, k1, v1);

    // Tensor-core attention: grid (8, 16, 8)
    dim3 agrid(Tlen / 128, NHEADS, Bsz);
    attn_mma<<<agrid, 256, ATT_SMEM>>>(qh, ql, k1, v1, ascl, ah, al);

    // Output projection (fp32 out)
    dim3 ogrid(EMB / 128, MTOT / 128);
    gemm_o_tc<<<ogrid, 256, SMEM_MMA>>>(ah, al, wo1, bo, out);
}

// round 15
// speedup vs baseline: 5.3429x; 1.6748x over previous
#include <cuda_runtime.h>
#include <cuda_fp16.h>
#include <math.h>
#include <stdint.h>

// Problem constants
#define Bsz    8
#define Tlen   1024
#define EMB    1024
#define NHEADS 16
#define HD     64

#define MTOT (Bsz * Tlen)          // 8192 rows

// ---------------------------------------------------------------------------
// Scratch (device globals — allocation-free per harness rules).
// Pure fp16 operands everywhere; fp32 accumulation in MMA.
// ---------------------------------------------------------------------------
__device__ __half g_x1[MTOT * EMB];
__device__ __half g_q1[MTOT * EMB];
__device__ __half g_k1[MTOT * EMB];
__device__ __half g_v1[MTOT * EMB];
__device__ __half g_a1[MTOT * EMB];
__device__ __half g_wq1[EMB * EMB], g_wk1[EMB * EMB];
__device__ __half g_wv1[EMB * EMB], g_wo1[EMB * EMB];

// ---------------------------------------------------------------------------
// Warp MMA helpers (mma.sync + ldmatrix — plain sm_103 features only)
// ---------------------------------------------------------------------------
__device__ __forceinline__ uint32_t smem_u32(const void* p) {
    uint32_t a;
    asm("{ .reg .u64 t; cvta.to.shared.u64 t, %1; cvt.u32.u64 %0, t; }"
        : "=r"(a) : "l"(p));
    return a;
}

__device__ __forceinline__ void ldsm_x4(uint32_t& r0, uint32_t& r1,
                                        uint32_t& r2, uint32_t& r3, uint32_t a) {
    asm volatile("ldmatrix.sync.aligned.m8n8.x4.shared.b16 {%0,%1,%2,%3}, [%4];"
                 : "=r"(r0), "=r"(r1), "=r"(r2), "=r"(r3) : "r"(a));
}
__device__ __forceinline__ void ldsm_x4_t(uint32_t* r, uint32_t a) {
    asm volatile("ldmatrix.sync.aligned.m8n8.x4.trans.shared.b16 {%0,%1,%2,%3}, [%4];"
                 : "=r"(r[0]), "=r"(r[1]), "=r"(r[2]), "=r"(r[3]) : "r"(a));
}
__device__ __forceinline__ void ldsm_x2(uint32_t& r0, uint32_t& r1, uint32_t a) {
    asm volatile("ldmatrix.sync.aligned.m8n8.x2.shared.b16 {%0,%1}, [%2];"
                 : "=r"(r0), "=r"(r1) : "r"(a));
}

__device__ __forceinline__ void mma16816(float* c, const uint32_t* a,
                                         const uint32_t* b) {
    asm volatile(
        "mma.sync.aligned.m16n8k16.row.col.f32.f16.f16.f32 "
        "{%0,%1,%2,%3}, {%4,%5,%6,%7}, {%8,%9}, {%0,%1,%2,%3};"
        : "+f"(c[0]), "+f"(c[1]), "+f"(c[2]), "+f"(c[3])
        : "r"(a[0]), "r"(a[1]), "r"(a[2]), "r"(a[3]), "r"(b[0]), "r"(b[1]));
}

__device__ __forceinline__ uint32_t pack2(float a, float b) {
    __half2 p; p.x = __float2half(a); p.y = __float2half(b);
    return *(uint32_t*)&p;
}

// ---------------------------------------------------------------------------
// fp32 -> fp16 conversion
// ---------------------------------------------------------------------------
__global__ __launch_bounds__(256)
void cvt_h(const float* __restrict__ s, __half* __restrict__ h, int n)
{
    int i = (blockIdx.x * 256 + threadIdx.x) * 4;
    if (i >= n) return;
    float4 v = *(const float4*)(s + i);
    *(__half2*)(h + i)     = __floats2half2_rn(v.x, v.y);
    *(__half2*)(h + i + 2) = __floats2half2_rn(v.z, v.w);
}

// ---------------------------------------------------------------------------
// fp16 tensor GEMM: C tile 128x128 of A[M,1024]*B[N,1024]^T + bias.
// fp32 accumulate. Smem: 2 tiles (A, B) of 128x(32+8) fp16, double-buffered.
// Epilogue: fp32 C (out-proj) or fp16 Ch (q/k/v/attn-out).
// ---------------------------------------------------------------------------
#define TCK   32
#define NCHK  (EMB / TCK)
#define TLD   40
#define TILE_B (128 * TLD * 2)
#define BUF_B  (2 * TILE_B)
#define SMEM_MMA (2 * BUF_B)        // 40960 B

__device__ __forceinline__
void ld_chunk(uint4* v, const __half* A0, const __half* B0,
              int row, int col, int kc)
{
    const size_t off = (size_t)row * EMB + kc + col;
    v[0] = *(const uint4*)(A0 + off); v[1] = *(const uint4*)(A0 + off + 8);
    v[2] = *(const uint4*)(B0 + off); v[3] = *(const uint4*)(B0 + off + 8);
}

__device__ __forceinline__
void st_chunk(char* smbuf, const uint4* v, int row, int col)
{
    const uint32_t off = (uint32_t)(row * TLD + col) * 2;
    *(uint4*)(smbuf + 0 * TILE_B + off)      = v[0];
    *(uint4*)(smbuf + 0 * TILE_B + off + 16) = v[1];
    *(uint4*)(smbuf + 1 * TILE_B + off)      = v[2];
    *(uint4*)(smbuf + 1 * TILE_B + off + 16) = v[3];
}

__device__ __forceinline__
void gemm_mma_body(const __half* __restrict__ a1, const __half* __restrict__ b1,
                   const float* __restrict__ bias,
                   float* __restrict__ C, __half* __restrict__ Ch,
                   int mBase, int nBase)
{
    extern __shared__ char sm[];
    const uint32_t smb = smem_u32(sm);

    const int tid  = threadIdx.x;
    const int wid  = tid >> 5;
    const int lane = tid & 31;
    const int wm = (wid >> 2) * 64;
    const int wn = (wid & 3) * 32;

    const int grow = tid >> 1;
    const int gcol = (tid & 1) * 16;

    const __half* A0 = a1 + (size_t)mBase * EMB;
    const __half* B0 = b1 + (size_t)nBase * EMB;

    const uint32_t aRow = wm + (lane & 15);
    const uint32_t aK   = (lane >> 4) * 8;
    const uint32_t bRow = wn + (lane & 7);
    const uint32_t bK   = ((lane >> 3) & 1) * 8;

    float acc[4][4][4];
#pragma unroll
    for (int mi = 0; mi < 4; mi++)
#pragma unroll
        for (int ni = 0; ni < 4; ni++)
#pragma unroll
            for (int e = 0; e < 4; e++) acc[mi][ni][e] = 0.f;

    {
        uint4 v[4];
        ld_chunk(v, A0, B0, grow, gcol, 0);
        st_chunk(sm, v, grow, gcol);
    }
    __syncthreads();

    int buf = 0;
    for (int c = 0; c < NCHK; c++) {
        const bool more = (c + 1) < NCHK;
        uint4 pf[4];
        if (more) ld_chunk(pf, A0, B0, grow, gcol, (c + 1) * TCK);

        const uint32_t bb = smb + buf * BUF_B;
#pragma unroll
        for (int k16 = 0; k16 < 2; k16++) {
            const uint32_t kb = k16 * 16;
            uint32_t fa[4][4], fb[4][2];
#pragma unroll
            for (int mi = 0; mi < 4; mi++) {
                uint32_t ao = ((aRow + mi * 16) * TLD + kb + aK) * 2;
                ldsm_x4(fa[mi][0], fa[mi][1], fa[mi][2], fa[mi][3],
                        bb + 0 * TILE_B + ao);
            }
#pragma unroll
            for (int ni = 0; ni < 4; ni++) {
                uint32_t bo = ((bRow + ni * 8) * TLD + kb + bK) * 2;
                ldsm_x2(fb[ni][0], fb[ni][1], bb + 1 * TILE_B + bo);
            }
#pragma unroll
            for (int mi = 0; mi < 4; mi++)
#pragma unroll
                for (int ni = 0; ni < 4; ni++)
                    mma16816(acc[mi][ni], fa[mi], fb[ni]);
        }

        if (more) {
            const int nb = buf ^ 1;
            st_chunk(sm + nb * BUF_B, pf, grow, gcol);
            __syncthreads();
            buf = nb;
        }
    }

    const int tr = lane >> 2;
    const int tc = (lane & 3) * 2;
#pragma unroll
    for (int mi = 0; mi < 4; mi++) {
        const int gm0 = mBase + wm + mi * 16 + tr;
#pragma unroll
        for (int ni = 0; ni < 4; ni++) {
            const int gn = nBase + wn + ni * 8 + tc;
            const float b0 = bias[gn], b1 = bias[gn + 1];
            float v0 = acc[mi][ni][0] + b0, v1 = acc[mi][ni][1] + b1;
            float v2 = acc[mi][ni][2] + b0, v3 = acc[mi][ni][3] + b1;
            if (C) {
                *(float2*)(C + (size_t)gm0 * EMB + gn)       = make_float2(v0, v1);
                *(float2*)(C + (size_t)(gm0 + 8) * EMB + gn) = make_float2(v2, v3);
            } else {
                *(__half2*)(Ch + (size_t)gm0 * EMB + gn)       = __floats2half2_rn(v0, v1);
                *(__half2*)(Ch + (size_t)(gm0 + 8) * EMB + gn) = __floats2half2_rn(v2, v3);
            }
        }
    }
}

// Fused QKV: grid (24, 64)
__global__ __launch_bounds__(256)
void gemm_qkv_tc(const __half* __restrict__ x1,
                 const __half* __restrict__ wq1, const __half* __restrict__ wk1,
                 const __half* __restrict__ wv1,
                 const float* __restrict__ bq, const float* __restrict__ bk,
                 const float* __restrict__ bv,
                 __half* __restrict__ q1, __half* __restrict__ k1,
                 __half* __restrict__ v1)
{
    const int sel = blockIdx.x >> 3;
    const int nb  = blockIdx.x & 7;
    const __half* wh  = (sel == 0) ? wq1 : (sel == 1) ? wk1 : wv1;
    const float* bias = (sel == 0) ? bq  : (sel == 1) ? bk  : bv;
    __half* Ch        = (sel == 0) ? q1  : (sel == 1) ? k1  : v1;
    gemm_mma_body(x1, wh, bias, nullptr, Ch, blockIdx.y * 128, nb * 128);
}

// Output projection (fp32 output): grid (8, 64)
__global__ __launch_bounds__(256)
void gemm_o_tc(const __half* __restrict__ a1, const __half* __restrict__ wo1,
               const float* __restrict__ bias, float* __restrict__ C)
{
    gemm_mma_body(a1, wo1, bias, C, nullptr, blockIdx.y * 128, blockIdx.x * 128);
}

// ---------------------------------------------------------------------------
// Tensor-core flash attention, pure fp16 operands, fp32 softmax/accum.
// CTA = (q-tile 128, head, batch); 8 warps x 16 q-rows. Key tiles of 64.
// Mask: only the diagonal 64-chunk tile, upper-triangular.
// ---------------------------------------------------------------------------
#define LDT 72
#define QH0 0
#define KH0 (128 * LDT)
#define VH0 (KH0 + 64 * LDT)
#define ATT_SMEM ((128 * LDT + 2 * 64 * LDT) * 2)   // 36,864 B

__global__ __launch_bounds__(256)
void attn_mma(const __half* __restrict__ q1, const __half* __restrict__ k1,
              const __half* __restrict__ v1, const float* __restrict__ scale_p,
              __half* __restrict__ o1)
{
    extern __shared__ char smc[];
    __half* sb = (__half*)smc;
    const uint32_t smb = smem_u32(smc);

    const int tid = threadIdx.x, wid = tid >> 5, lane = tid & 31;
    const int wq = wid * 16;
    const int qt = blockIdx.x, h = blockIdx.y, b = blockIdx.z;
    const float scale = scale_p[0];
    const int tr  = lane >> 2;
    const int tc2 = 2 * (lane & 3);

    // ---- load Q tile ----
    {
        const int r = tid >> 1, c = (tid & 1) * 32;
        const size_t go = ((size_t)(b * Tlen + qt * 128 + r)) * EMB + h * HD + c;
        const uint4* s0 = (const uint4*)(q1 + go);
        uint4* d0 = (uint4*)(sb + QH0 + r * LDT + c);
#pragma unroll
        for (int j = 0; j < 4; j++) d0[j] = s0[j];
    }
    __syncthreads();

    // ---- Q A-frags, hoisted ----
    uint32_t fq[4][4];
    {
        const uint32_t arow = wq + (lane & 15);
        const uint32_t akk  = (lane >> 4) * 8;
#pragma unroll
        for (int ks = 0; ks < 4; ks++)
            ldsm_x4(fq[ks][0], fq[ks][1], fq[ks][2], fq[ks][3],
                    smb + (QH0 + arow * LDT + ks * 16 + akk) * 2);
    }

    float m0 = -INFINITY, m1 = -INFINITY, l0 = 0.f, l1 = 0.f;
    float o[8][4];
#pragma unroll
    for (int nd = 0; nd < 8; nd++)
#pragma unroll
        for (int e = 0; e < 4; e++) o[nd][e] = 0.f;

    const int ktd  = qt * 2 + (wid >> 2);
    const int rel0 = (wid & 3) * 16 + tr;

    for (int kt = 0; kt < 16; kt++) {
        __syncthreads();
        {   // load K/V tiles, 64x64 each
            const int r = tid >> 2, c = (tid & 3) * 16;
            const size_t go = ((size_t)(b * Tlen + kt * 64 + r)) * EMB + h * HD + c;
            uint4* dk = (uint4*)(sb + KH0 + r * LDT + c);
            uint4* dv = (uint4*)(sb + VH0 + r * LDT + c);
            const uint4* skp = (const uint4*)(k1 + go);
            const uint4* svp = (const uint4*)(v1 + go);
#pragma unroll
            for (int j = 0; j < 2; j++) { dk[j] = skp[j]; dv[j] = svp[j]; }
        }
        __syncthreads();

        // ---- S = Q.K^T ----
        float s[8][4];
#pragma unroll
        for (int ni = 0; ni < 8; ni++)
#pragma unroll
            for (int e = 0; e < 4; e++) s[ni][e] = 0.f;

#pragma unroll
        for (int ni = 0; ni < 8; ni += 2) {
#pragma unroll
            for (int ks = 0; ks < 4; ks++) {
                uint32_t kh4[4];
                const uint32_t boff =
                    ((ni + (lane >> 4)) * 8 + (lane & 7)) * LDT
                    + ks * 16 + ((lane >> 3) & 1) * 8;
                ldsm_x4(kh4[0], kh4[1], kh4[2], kh4[3], smb + (KH0 + boff) * 2);
                mma16816(s[ni],     fq[ks], kh4);
                mma16816(s[ni + 1], fq[ks], kh4 + 2);
            }
        }

        // scale + mask (diagonal chunk tile only)
#pragma unroll
        for (int ni = 0; ni < 8; ni++)
#pragma unroll
            for (int e = 0; e < 4; e++) s[ni][e] *= scale;
        if (kt == ktd) {
#pragma unroll
            for (int ni = 0; ni < 8; ni++) {
                const int c0 = ni * 8 + tc2;
                if (c0     > rel0)     s[ni][0] = -INFINITY;
                if (c0 + 1 > rel0)     s[ni][1] = -INFINITY;
                if (c0     > rel0 + 8) s[ni][2] = -INFINITY;
                if (c0 + 1 > rel0 + 8) s[ni][3] = -INFINITY;
            }
        }

        // ---- online softmax (rows tr and tr+8) ----
        float tm0 = -INFINITY, tm1 = -INFINITY;
#pragma unroll
        for (int ni = 0; ni < 8; ni++) {
            tm0 = fmaxf(tm0, fmaxf(s[ni][0], s[ni][1]));
            tm1 = fmaxf(tm1, fmaxf(s[ni][2], s[ni][3]));
        }
        tm0 = fmaxf(tm0, __shfl_xor_sync(0xffffffffu, tm0, 1));
        tm0 = fmaxf(tm0, __shfl_xor_sync(0xffffffffu, tm0, 2));
        tm1 = fmaxf(tm1, __shfl_xor_sync(0xffffffffu, tm1, 1));
        tm1 = fmaxf(tm1, __shfl_xor_sync(0xffffffffu, tm1, 2));
        const float mn0 = fmaxf(m0, tm0), mn1 = fmaxf(m1, tm1);
        const float co0 = __expf(m0 - mn0), co1 = __expf(m1 - mn1);

        float ts0 = 0.f, ts1 = 0.f;
#pragma unroll
        for (int ni = 0; ni < 8; ni++) {
            s[ni][0] = __expf(s[ni][0] - mn0); ts0 += s[ni][0];
            s[ni][1] = __expf(s[ni][1] - mn0); ts0 += s[ni][1];
            s[ni][2] = __expf(s[ni][2] - mn1); ts1 += s[ni][2];
            s[ni][3] = __expf(s[ni][3] - mn1); ts1 += s[ni][3];
        }
        ts0 += __shfl_xor_sync(0xffffffffu, ts0, 1);
        ts0 += __shfl_xor_sync(0xffffffffu, ts0, 2);
        ts1 += __shfl_xor_sync(0xffffffffu, ts1, 1);
        ts1 += __shfl_xor_sync(0xffffffffu, ts1, 2);
        l0 = l0 * co0 + ts0; l1 = l1 * co1 + ts1;
        m0 = mn0; m1 = mn1;
#pragma unroll
        for (int nd = 0; nd < 8; nd++) {
            o[nd][0] *= co0; o[nd][1] *= co0;
            o[nd][2] *= co1; o[nd][3] *= co1;
        }

        // ---- O += P.V (P packed to fp16; V via ldmatrix.trans) ----
#pragma unroll
        for (int kp = 0; kp < 4; kp++) {
            uint32_t fp[4];
            fp[0] = pack2(s[2 * kp][0],     s[2 * kp][1]);
            fp[1] = pack2(s[2 * kp][2],     s[2 * kp][3]);
            fp[2] = pack2(s[2 * kp + 1][0], s[2 * kp + 1][1]);
            fp[3] = pack2(s[2 * kp + 1][2], s[2 * kp + 1][3]);
#pragma unroll
            for (int nd = 0; nd < 8; nd += 2) {
                uint32_t fv[4];
                const uint32_t voff =
                    (kp * 16 + (lane & 15)) * LDT + (nd + (lane >> 4)) * 8;
                ldsm_x4_t(fv, smb + (VH0 + voff) * 2);
                mma16816(o[nd],     fp, fv);
                mma16816(o[nd + 1], fp, fv + 2);
            }
        }
    }

    // ---- finalize: normalize, store fp16 ----
    const float i0 = 1.f / l0, i1 = 1.f / l1;
    const size_t row0 = (size_t)(b * Tlen + qt * 128 + wq + tr);
#pragma unroll
    for (int nd = 0; nd < 8; nd++) {
        const int col = h * HD + nd * 8 + tc2;
        *(__half2*)(o1 + row0 * EMB + col) =
            __floats2half2_rn(o[nd][0] * i0, o[nd][1] * i0);
        *(__half2*)(o1 + (row0 + 8) * EMB + col) =
            __floats2half2_rn(o[nd][2] * i1, o[nd][3] * i1);
    }
}

// ---------------------------------------------------------------------------
// Launch
// ---------------------------------------------------------------------------
extern "C" void kernel_launch(void* const* d_in, const int* in_sizes, int n_in,
                              void* d_out, int out_size)
{
    const float* x     = (const float*)d_in[0];
    const float* Wq    = (const float*)d_in[1];
    const float* bq    = (const float*)d_in[2];
    const float* Wk    = (const float*)d_in[3];
    const float* bk    = (const float*)d_in[4];
    const float* Wv    = (const float*)d_in[5];
    const float* bv    = (const float*)d_in[6];
    const float* Wo    = (const float*)d_in[7];
    const float* bo    = (const float*)d_in[8];
    const float* ascl  = (const float*)d_in[9];
    float* out = (float*)d_out;

    __half *x1, *q1, *k1, *v1, *a1, *wq1, *wk1, *wv1, *wo1;
    cudaGetSymbolAddress((void**)&x1, g_x1);
    cudaGetSymbolAddress((void**)&q1, g_q1);
    cudaGetSymbolAddress((void**)&k1, g_k1);
    cudaGetSymbolAddress((void**)&v1, g_v1);
    cudaGetSymbolAddress((void**)&a1, g_a1);
    cudaGetSymbolAddress((void**)&wq1, g_wq1);
    cudaGetSymbolAddress((void**)&wk1, g_wk1);
    cudaGetSymbolAddress((void**)&wv1, g_wv1);
    cudaGetSymbolAddress((void**)&wo1, g_wo1);

    const int nX = MTOT * EMB;     // 8M
    const int nW = EMB * EMB;      // 1M
    cvt_h<<<nX / 1024, 256>>>(x, x1, nX);
    cvt_h<<<nW / 1024, 256>>>(Wq, wq1, nW);
    cvt_h<<<nW / 1024, 256>>>(Wk, wk1, nW);
    cvt_h<<<nW / 1024, 256>>>(Wv, wv1, nW);
    cvt_h<<<nW / 1024, 256>>>(Wo, wo1, nW);

    cudaFuncSetAttribute(gemm_qkv_tc, cudaFuncAttributeMaxDynamicSharedMemorySize, SMEM_MMA);
    cudaFuncSetAttribute(gemm_o_tc,   cudaFuncAttributeMaxDynamicSharedMemorySize, SMEM_MMA);
    cudaFuncSetAttribute(attn_mma,    cudaFuncAttributeMaxDynamicSharedMemorySize, ATT_SMEM);

    // QKV projections: grid (24, 64)
    dim3 qkvGrid(24, MTOT / 128);
    gemm_qkv_tc<<<qkvGrid, 256, SMEM_MMA>>>(x1, wq1, wk1, wv1,
                                            bq, bk, bv, q1, k1, v1);

    // Tensor-core attention: grid (8, 16, 8)
    dim3 agrid(Tlen / 128, NHEADS, Bsz);
    attn_mma<<<agrid, 256, ATT_SMEM>>>(q1, k1, v1, ascl, a1);

    // Output projection (fp32 out)
    dim3 ogrid(EMB / 128, MTOT / 128);
    gemm_o_tc<<<ogrid, 256, SMEM_MMA>>>(a1, wo1, bo, out);
}